// round 4
// baseline (speedup 1.0000x reference)
#include <cuda_runtime.h>
#include <math.h>
#include <stdint.h>

// ---------------- problem constants ----------------
#define BB    2
#define NN    2048
#define CCH   512
#define KVL   2560          // CCH + NN
#define DM    768
#define NH    12
#define HD    64
#define FF    3072
#define KSZ   31
#define RR    (BB*NN)       // 4096 token rows
#define EPS   1e-5f

// ---------------- scratch (static device memory; no allocs) ----------------
__device__ float g_x   [RR*DM];          // running residual
__device__ float g_norm[RR*DM];          // rmsnorm output
__device__ float g_ff  [RR*FF];          // FF hidden / pw1 output
__device__ float g_qkv [RR*3*NH*HD];     // qkv projection
__device__ float g_qrot[RR*DM];          // roped q  (b,n,h,d)
__device__ float g_krot[BB*KVL*DM];      // roped k  (b,p,h,d)
__device__ float g_attn[RR*DM];          // attention output pre-proj
__device__ float g_glu [RR*DM];          // GLU out / BN+swish out
__device__ float g_dw  [RR*DM];          // depthwise conv out
__device__ float g_mean[DM];
__device__ float g_var [DM];

// ---------------- rmsnorm: one block per row ----------------
__global__ void rmsnorm_k(const float* __restrict__ x, const float* __restrict__ w,
                          float* __restrict__ y) {
    int r = blockIdx.x, tid = threadIdx.x;
    const float* xr = x + (size_t)r*DM;
    float ss = 0.f;
    for (int i = tid; i < DM; i += 256) { float v = xr[i]; ss += v*v; }
    __shared__ float red[256];
    red[tid] = ss; __syncthreads();
    for (int s = 128; s > 0; s >>= 1) { if (tid < s) red[tid] += red[tid+s]; __syncthreads(); }
    float rs = rsqrtf(red[0] * (1.f/DM) + EPS);
    float* yr = y + (size_t)r*DM;
    for (int i = tid; i < DM; i += 256) yr[i] = xr[i]*rs*w[i];
}

// ---------------- generic SGEMM 64x64x16, fused epilogue ----------------
// ACT: 0 = v+bias ; 1 = gelu(v+bias) ; 2 = 0.5*(v+bias).  resid != nullptr adds residual.
template<int ACT>
__global__ void sgemm_k(const float* __restrict__ A, const float* __restrict__ W,
                        const float* __restrict__ bias, const float* __restrict__ resid,
                        float* __restrict__ C, int M, int Nn, int K) {
    __shared__ float As[16][64];
    __shared__ float Bs[16][64];
    int tid = threadIdx.x;
    int bm = blockIdx.y*64, bn = blockIdx.x*64;
    int am = tid >> 2, ak = (tid & 3) * 4;          // A tile load coords
    int bk = tid >> 4, bnn = (tid & 15) * 4;        // B tile load coords
    int tm = (tid >> 4) * 4, tn = (tid & 15) * 4;   // compute coords
    float acc[4][4] = {};
    for (int k0 = 0; k0 < K; k0 += 16) {
        float4 av = *(const float4*)&A[(size_t)(bm+am)*K + k0 + ak];
        As[ak+0][am] = av.x; As[ak+1][am] = av.y; As[ak+2][am] = av.z; As[ak+3][am] = av.w;
        *(float4*)&Bs[bk][bnn] = *(const float4*)&W[(size_t)(k0+bk)*Nn + bn + bnn];
        __syncthreads();
        #pragma unroll
        for (int kk = 0; kk < 16; kk++) {
            float4 a4 = *(const float4*)&As[kk][tm];
            float4 b4 = *(const float4*)&Bs[kk][tn];
            float ar[4] = {a4.x, a4.y, a4.z, a4.w};
            float br[4] = {b4.x, b4.y, b4.z, b4.w};
            #pragma unroll
            for (int i = 0; i < 4; i++)
                #pragma unroll
                for (int j = 0; j < 4; j++)
                    acc[i][j] += ar[i]*br[j];
        }
        __syncthreads();
    }
    #pragma unroll
    for (int i = 0; i < 4; i++) {
        int gr = bm + tm + i;
        #pragma unroll
        for (int j = 0; j < 4; j++) {
            int gc = bn + tn + j;
            float v = acc[i][j] + (bias ? bias[gc] : 0.f);
            if (ACT == 1) {                 // jax.nn.gelu (tanh approx)
                float t = v;
                v = 0.5f*t*(1.f + tanhf(0.7978845608028654f*(t + 0.044715f*t*t*t)));
            }
            if (ACT == 2) v *= 0.5f;
            if (resid) v += resid[(size_t)gr*Nn + gc];
            C[(size_t)gr*Nn + gc] = v;
        }
    }
}

// ---------------- kv cache copy: cached_kv -> d_out kv region ----------------
__global__ void copy_cache_k(const float* __restrict__ cached, float* __restrict__ kvout) {
    int idx = blockIdx.x*blockDim.x + threadIdx.x;
    const int per = CCH*2*NH*HD;            // per-batch cached elements
    const int tot = BB*per;
    if (idx >= tot) return;
    int b = idx / per, r = idx % per;
    kvout[(size_t)b*KVL*2*NH*HD + r] = cached[idx];
}

// ---------------- qkv post: per-head rmsnorm, write K/V to cache, rope Q ----------------
__global__ void qkv_post_k(const float* __restrict__ qkv, const float* __restrict__ qw,
                           const float* __restrict__ kw, float* __restrict__ kvout,
                           float* __restrict__ qrot) {
    int w = (blockIdx.x*blockDim.x + threadIdx.x) >> 5;
    int lane = threadIdx.x & 31;
    if (w >= RR*NH) return;
    int b = w / (NN*NH), rem = w % (NN*NH);
    int n = rem / NH, h = rem % NH;
    const float* base = qkv + (size_t)(b*NN + n)*(3*NH*HD) + h*HD*3;
    float q0 = base[lane*3+0],      q1 = base[(lane+32)*3+0];
    float k0 = base[lane*3+1],      k1 = base[(lane+32)*3+1];
    float v0 = base[lane*3+2],      v1 = base[(lane+32)*3+2];
    float ssq = q0*q0 + q1*q1, ssk = k0*k0 + k1*k1;
    #pragma unroll
    for (int off = 16; off; off >>= 1) {
        ssq += __shfl_xor_sync(0xffffffffu, ssq, off);
        ssk += __shfl_xor_sync(0xffffffffu, ssk, off);
    }
    float rq = rsqrtf(ssq*(1.f/HD) + EPS);
    float rk = rsqrtf(ssk*(1.f/HD) + EPS);
    q0 *= rq*qw[lane]; q1 *= rq*qw[lane+32];
    k0 *= rk*kw[lane]; k1 *= rk*kw[lane+32];
    // store normalized k and raw v into kv cache output
    size_t ko = ((((size_t)b*KVL + CCH + n)*2 + 0)*NH + h)*HD;
    kvout[ko + lane] = k0;            kvout[ko + lane + 32] = k1;
    size_t vo = ko + (size_t)NH*HD;   // s=1 slice
    kvout[vo + lane] = v0;            kvout[vo + lane + 32] = v1;
    // rope q at pos = CCH + n
    double inv = exp(-(double)lane * 0.28782313662425575);   // ln(10000)/32
    double ang = (double)(CCH + n) * inv;
    double sd, cd; sincos(ang, &sd, &cd);
    float s = (float)sd, c = (float)cd;
    size_t qo = ((size_t)(b*NN + n)*NH + h)*HD;
    qrot[qo + lane]      = q0*c - q1*s;
    qrot[qo + lane + 32] = q1*c + q0*s;
}

// ---------------- rope over the full K cache ----------------
__global__ void rope_k_k(const float* __restrict__ kvout, float* __restrict__ krot) {
    int w = (blockIdx.x*blockDim.x + threadIdx.x) >> 5;
    int lane = threadIdx.x & 31;
    if (w >= BB*KVL*NH) return;
    int b = w / (KVL*NH), rem = w % (KVL*NH);
    int p = rem / NH, h = rem % NH;
    size_t ko = ((((size_t)b*KVL + p)*2 + 0)*NH + h)*HD;
    float k0 = kvout[ko + lane], k1 = kvout[ko + lane + 32];
    double inv = exp(-(double)lane * 0.28782313662425575);
    double ang = (double)p * inv;
    double sd, cd; sincos(ang, &sd, &cd);
    float s = (float)sd, c = (float)cd;
    size_t o = ((size_t)(b*KVL + p)*NH + h)*HD;
    krot[o + lane]      = k0*c - k1*s;
    krot[o + lane + 32] = k1*c + k0*s;
}

// ---------------- flash attention: block per (b,h,64-query tile) ----------------
// 128 threads: ty = t>>3 (0..15) owns 4 query rows; tx = t&7 owns 8 cols/dims.
#define BQ   64
#define BK   64
#define APAD 65
__global__ void flash_attn_k(const float* __restrict__ qrot, const float* __restrict__ krot,
                             const float* __restrict__ kvout, float* __restrict__ out) {
    extern __shared__ float sm[];
    float* Qs = sm;                    // BQ*APAD
    float* Ks = Qs + BQ*APAD;          // BK*APAD
    float* Vs = Ks + BK*APAD;          // BK*APAD
    float* Ps = Vs + BK*APAD;          // BQ*APAD
    int qt = blockIdx.x, h = blockIdx.y, b = blockIdx.z;
    int t = threadIdx.x;
    int ty = t >> 3, tx = t & 7;

    // load Q tile (scaled)
    for (int idx = t; idx < BQ*16; idx += 128) {
        int r = idx >> 4, c4 = (idx & 15) * 4;
        int q = qt*BQ + r;
        float4 v = *(const float4*)&qrot[((size_t)(b*NN + q)*NH + h)*HD + c4];
        Qs[r*APAD + c4+0] = v.x * 0.125f;  // 1/sqrt(64)
        Qs[r*APAD + c4+1] = v.y * 0.125f;
        Qs[r*APAD + c4+2] = v.z * 0.125f;
        Qs[r*APAD + c4+3] = v.w * 0.125f;
    }

    float acc[4][8] = {};
    float m_r[4] = {-1e30f,-1e30f,-1e30f,-1e30f};
    float l_r[4] = {};

    for (int p0 = 0; p0 < KVL; p0 += BK) {
        __syncthreads();   // protect Ks/Vs from previous iteration readers (and Q on first pass)
        for (int idx = t; idx < BK*16; idx += 128) {
            int j = idx >> 4, c4 = (idx & 15) * 4;
            int p = p0 + j;
            float4 kv = *(const float4*)&krot[((size_t)(b*KVL + p)*NH + h)*HD + c4];
            Ks[j*APAD + c4+0] = kv.x; Ks[j*APAD + c4+1] = kv.y;
            Ks[j*APAD + c4+2] = kv.z; Ks[j*APAD + c4+3] = kv.w;
            float4 vv = *(const float4*)&kvout[(((size_t)(b*KVL + p)*2 + 1)*NH + h)*HD + c4];
            Vs[j*APAD + c4+0] = vv.x; Vs[j*APAD + c4+1] = vv.y;
            Vs[j*APAD + c4+2] = vv.z; Vs[j*APAD + c4+3] = vv.w;
        }
        __syncthreads();

        // scores s[i][jj] = Q[ty*4+i] . K[tx*8+jj]
        float s[4][8] = {};
        #pragma unroll 8
        for (int d = 0; d < HD; d++) {
            float qv[4], kv[8];
            #pragma unroll
            for (int i = 0; i < 4; i++) qv[i] = Qs[(ty*4+i)*APAD + d];
            #pragma unroll
            for (int jj = 0; jj < 8; jj++) kv[jj] = Ks[(tx*8+jj)*APAD + d];
            #pragma unroll
            for (int i = 0; i < 4; i++)
                #pragma unroll
                for (int jj = 0; jj < 8; jj++)
                    s[i][jj] += qv[i]*kv[jj];
        }

        // online softmax update per row (reduce over the 8 tx lanes)
        #pragma unroll
        for (int i = 0; i < 4; i++) {
            float mx = s[i][0];
            #pragma unroll
            for (int jj = 1; jj < 8; jj++) mx = fmaxf(mx, s[i][jj]);
            #pragma unroll
            for (int off = 1; off < 8; off <<= 1)
                mx = fmaxf(mx, __shfl_xor_sync(0xffffffffu, mx, off));
            float mn = fmaxf(m_r[i], mx);
            float corr = __expf(m_r[i] - mn);
            m_r[i] = mn;
            float ls = 0.f;
            #pragma unroll
            for (int jj = 0; jj < 8; jj++) {
                float e = __expf(s[i][jj] - mn);
                Ps[(ty*4+i)*APAD + tx*8+jj] = e;
                ls += e;
            }
            #pragma unroll
            for (int off = 1; off < 8; off <<= 1)
                ls += __shfl_xor_sync(0xffffffffu, ls, off);
            l_r[i] = l_r[i]*corr + ls;
            #pragma unroll
            for (int dd = 0; dd < 8; dd++) acc[i][dd] *= corr;
        }
        __syncthreads();   // Ps fully written before cross-thread reads

        // acc[i][dd] += P[r][j] * V[j][tx*8+dd]
        #pragma unroll 8
        for (int j = 0; j < BK; j++) {
            float pv[4], vv[8];
            #pragma unroll
            for (int i = 0; i < 4; i++) pv[i] = Ps[(ty*4+i)*APAD + j];
            #pragma unroll
            for (int dd = 0; dd < 8; dd++) vv[dd] = Vs[j*APAD + tx*8+dd];
            #pragma unroll
            for (int i = 0; i < 4; i++)
                #pragma unroll
                for (int dd = 0; dd < 8; dd++)
                    acc[i][dd] += pv[i]*vv[dd];
        }
    }

    // epilogue
    #pragma unroll
    for (int i = 0; i < 4; i++) {
        float rl = 1.f / l_r[i];
        int q = qt*BQ + ty*4 + i;
        size_t o = ((size_t)(b*NN + q)*NH + h)*HD + tx*8;
        #pragma unroll
        for (int dd = 0; dd < 8; dd++) out[o + dd] = acc[i][dd]*rl;
    }
}

// ---------------- GLU: a * sigmoid(g) ----------------
__global__ void glu_k(const float* __restrict__ in, float* __restrict__ out) {
    int idx = blockIdx.x*blockDim.x + threadIdx.x;
    if (idx >= RR*DM) return;
    int r = idx / DM, c = idx % DM;
    float a = in[(size_t)r*(2*DM) + c];
    float g = in[(size_t)r*(2*DM) + DM + c];
    out[idx] = a / (1.f + expf(-g));
}

// ---------------- depthwise conv over time (per batch, pad 15) ----------------
__global__ void dwconv_k(const float* __restrict__ in, const float* __restrict__ w,
                         const float* __restrict__ bias, float* __restrict__ out) {
    int idx = blockIdx.x*blockDim.x + threadIdx.x;
    if (idx >= RR*DM) return;
    int c = idx % DM, bn = idx / DM;
    int n = bn % NN, b = bn / NN;
    const float* wr = w + c*KSZ;
    const float* base = in + (size_t)b*NN*DM + c;
    float acc = bias[c];
    #pragma unroll
    for (int t = 0; t < KSZ; t++) {
        int nn = n + t - (KSZ/2);
        if (nn >= 0 && nn < NN) acc += base[(size_t)nn*DM] * wr[t];
    }
    out[idx] = acc;
}

// ---------------- batchnorm stats (per channel over B*N) ----------------
__global__ void bnstats_k(const float* __restrict__ x, float* __restrict__ mean,
                          float* __restrict__ var) {
    int c = blockIdx.x, tid = threadIdx.x;
    float s = 0.f, s2 = 0.f;
    for (int r = tid; r < RR; r += 256) {
        float v = x[(size_t)r*DM + c];
        s += v; s2 += v*v;
    }
    __shared__ float rs[256], rs2[256];
    rs[tid] = s; rs2[tid] = s2; __syncthreads();
    for (int k = 128; k > 0; k >>= 1) {
        if (tid < k) { rs[tid] += rs[tid+k]; rs2[tid] += rs2[tid+k]; }
        __syncthreads();
    }
    if (tid == 0) {
        float m = rs[0] * (1.f/RR);
        mean[c] = m;
        var[c] = rs2[0] * (1.f/RR) - m*m;
    }
}

// ---------------- batchnorm apply + swish ----------------
__global__ void bnapply_k(const float* __restrict__ x, const float* __restrict__ mean,
                          const float* __restrict__ var, const float* __restrict__ g,
                          const float* __restrict__ b, float* __restrict__ out) {
    int idx = blockIdx.x*blockDim.x + threadIdx.x;
    if (idx >= RR*DM) return;
    int c = idx % DM;
    float v = (x[idx] - mean[c]) * rsqrtf(var[c] + EPS) * g[c] + b[c];
    out[idx] = v / (1.f + expf(-v));           // swish
}

// ---------------- launch ----------------
extern "C" void kernel_launch(void* const* d_in, const int* in_sizes, int n_in,
                              void* d_out, int out_size) {
    const float* x_in      = (const float*)d_in[0];
    // d_in[1] attn_mask (all true), d_in[2] pad_mask (all false), d_in[3] length: no-ops
    const float* cached    = (const float*)d_in[4];
    const float* ff1_nw    = (const float*)d_in[5];
    const float* ff1_w1    = (const float*)d_in[6];
    const float* ff1_b1    = (const float*)d_in[7];
    const float* ff1_w2    = (const float*)d_in[8];
    const float* ff1_b2    = (const float*)d_in[9];
    const float* attn_nw   = (const float*)d_in[10];
    const float* qkv_w     = (const float*)d_in[11];
    const float* out_w     = (const float*)d_in[12];
    const float* q_nw      = (const float*)d_in[13];
    const float* k_nw      = (const float*)d_in[14];
    const float* conv_nw   = (const float*)d_in[15];
    const float* pw1_w     = (const float*)d_in[16];
    const float* pw1_b     = (const float*)d_in[17];
    const float* dw_w      = (const float*)d_in[18];
    const float* dw_b      = (const float*)d_in[19];
    const float* bn_g      = (const float*)d_in[20];
    const float* bn_b      = (const float*)d_in[21];
    const float* pw2_w     = (const float*)d_in[22];
    const float* pw2_b     = (const float*)d_in[23];
    const float* ff2_nw    = (const float*)d_in[24];
    const float* ff2_w1    = (const float*)d_in[25];
    const float* ff2_b1    = (const float*)d_in[26];
    const float* ff2_w2    = (const float*)d_in[27];
    const float* ff2_b2    = (const float*)d_in[28];
    const float* out_nw    = (const float*)d_in[29];

    float* outx  = (float*)d_out;
    float* kvout = outx + (size_t)RR*DM;

    float *x_, *norm_, *ff_, *qkv_, *qrot_, *krot_, *attn_, *glu_, *dw_, *mean_, *var_;
    cudaGetSymbolAddress((void**)&x_,    g_x);
    cudaGetSymbolAddress((void**)&norm_, g_norm);
    cudaGetSymbolAddress((void**)&ff_,   g_ff);
    cudaGetSymbolAddress((void**)&qkv_,  g_qkv);
    cudaGetSymbolAddress((void**)&qrot_, g_qrot);
    cudaGetSymbolAddress((void**)&krot_, g_krot);
    cudaGetSymbolAddress((void**)&attn_, g_attn);
    cudaGetSymbolAddress((void**)&glu_,  g_glu);
    cudaGetSymbolAddress((void**)&dw_,   g_dw);
    cudaGetSymbolAddress((void**)&mean_, g_mean);
    cudaGetSymbolAddress((void**)&var_,  g_var);

    static int smem_set = 0;
    if (!smem_set) {
        cudaFuncSetAttribute(flash_attn_k, cudaFuncAttributeMaxDynamicSharedMemorySize,
                             4*BQ*APAD*sizeof(float));
        smem_set = 1;
    }

    cudaMemcpyAsync(x_, x_in, sizeof(float)*(size_t)RR*DM, cudaMemcpyDeviceToDevice, 0);

    const int EW = (RR*DM + 255)/256;

    // ---- FF1: x = 0.5*(gelu(rms(x)@w1+b1)@w2 + b2) + x
    rmsnorm_k<<<RR, 256>>>(x_, ff1_nw, norm_);
    sgemm_k<1><<<dim3(FF/64, RR/64), 256>>>(norm_, ff1_w1, ff1_b1, nullptr, ff_, RR, FF, DM);
    sgemm_k<2><<<dim3(DM/64, RR/64), 256>>>(ff_, ff1_w2, ff1_b2, x_, x_, RR, DM, FF);

    // ---- Attention
    rmsnorm_k<<<RR, 256>>>(x_, attn_nw, norm_);
    sgemm_k<0><<<dim3((3*NH*HD)/64, RR/64), 256>>>(norm_, qkv_w, nullptr, nullptr, qkv_, RR, 3*NH*HD, DM);
    copy_cache_k<<<(BB*CCH*2*NH*HD + 255)/256, 256>>>(cached, kvout);
    qkv_post_k<<<RR*NH/4, 128>>>(qkv_, q_nw, k_nw, kvout, qrot_);
    rope_k_k<<<BB*KVL*NH/4, 128>>>(kvout, krot_);
    flash_attn_k<<<dim3(NN/BQ, NH, BB), 128, 4*BQ*APAD*sizeof(float)>>>(qrot_, krot_, kvout, attn_);
    sgemm_k<0><<<dim3(DM/64, RR/64), 256>>>(attn_, out_w, nullptr, x_, x_, RR, DM, DM);

    // ---- Conv module (replaces x; no residual)
    rmsnorm_k<<<RR, 256>>>(x_, conv_nw, norm_);
    sgemm_k<0><<<dim3((2*DM)/64, RR/64), 256>>>(norm_, pw1_w, pw1_b, nullptr, ff_, RR, 2*DM, DM);
    glu_k<<<EW, 256>>>(ff_, glu_);
    dwconv_k<<<EW, 256>>>(glu_, dw_w, dw_b, dw_);
    bnstats_k<<<DM, 256>>>(dw_, mean_, var_);
    bnapply_k<<<EW, 256>>>(dw_, mean_, var_, bn_g, bn_b, glu_);
    sgemm_k<0><<<dim3(DM/64, RR/64), 256>>>(glu_, pw2_w, pw2_b, nullptr, x_, RR, DM, DM);

    // ---- FF2
    rmsnorm_k<<<RR, 256>>>(x_, ff2_nw, norm_);
    sgemm_k<1><<<dim3(FF/64, RR/64), 256>>>(norm_, ff2_w1, ff2_b1, nullptr, ff_, RR, FF, DM);
    sgemm_k<2><<<dim3(DM/64, RR/64), 256>>>(ff_, ff2_w2, ff2_b2, x_, x_, RR, DM, FF);

    // ---- final rmsnorm -> output x
    rmsnorm_k<<<RR, 256>>>(x_, out_nw, outx);
}

// round 10
// speedup vs baseline: 1.7282x; 1.7282x over previous
#include <cuda_runtime.h>
#include <cuda_bf16.h>
#include <math.h>
#include <stdint.h>

// ---------------- problem constants ----------------
#define BB    2
#define NN    2048
#define CCH   512
#define KVL   2560          // CCH + NN
#define DM    768
#define NH    12
#define HD    64
#define FF    3072
#define KSZ   31
#define RR    (BB*NN)       // 4096 token rows
#define EPS   1e-5f

// ---------------- scratch (static device memory; no allocs) ----------------
__device__ float g_x   [RR*DM];
__device__ float g_norm[RR*DM];
__device__ float g_ff  [RR*FF];
__device__ float g_qkv [RR*3*NH*HD];
__device__ float g_qrot[RR*DM];
__device__ float g_krot[BB*KVL*DM];
__device__ float g_attn[RR*DM];
__device__ float g_glu [RR*DM];
__device__ float g_dw  [RR*DM];
__device__ float g_mean[DM];
__device__ float g_var [DM];
__device__ float g_rs  [KVL*32];         // rope sin table
__device__ float g_rc  [KVL*32];         // rope cos table

#define WT_TOTAL 13565952
__device__ __align__(256) __nv_bfloat16 g_wth[WT_TOTAL];   // transposed weights hi
__device__ __align__(256) __nv_bfloat16 g_wtl[WT_TOTAL];   // transposed weights lo
__device__ __align__(256) __nv_bfloat16 g_abh[RR*FF];      // activation split hi
__device__ __align__(256) __nv_bfloat16 g_abl[RR*FF];      // activation split lo

// ================= PTX helpers (base sm_103-safe: cp.async / ldmatrix / mma.sync only) ====
__device__ __forceinline__ uint32_t _s2u(const void* p){
    uint32_t a; asm("{ .reg .u64 t; cvta.to.shared.u64 t, %1; cvt.u32.u64 %0, t; }":"=r"(a):"l"(p)); return a;
}
#define CP16(d,s)   asm volatile("cp.async.cg.shared.global [%0], [%1], 16;"::"r"(d),"l"(s):"memory")
#define CPCOMMIT()  asm volatile("cp.async.commit_group;":::"memory")
#define CPWAITG(n)  asm volatile("cp.async.wait_group %0;"::"n"(n):"memory")

__device__ __forceinline__ void ldsm_x4(uint32_t a, uint32_t r[4]){
    asm volatile("ldmatrix.sync.aligned.m8n8.x4.shared.b16 {%0,%1,%2,%3}, [%4];"
        : "=r"(r[0]),"=r"(r[1]),"=r"(r[2]),"=r"(r[3]) : "r"(a));
}
__device__ __forceinline__ void ldsm_x2(uint32_t a, uint32_t r[2]){
    asm volatile("ldmatrix.sync.aligned.m8n8.x2.shared.b16 {%0,%1}, [%2];"
        : "=r"(r[0]),"=r"(r[1]) : "r"(a));
}
__device__ __forceinline__ void mma16816(float d[4], const uint32_t a[4], const uint32_t b[2]){
    asm volatile("mma.sync.aligned.m16n8k16.row.col.f32.bf16.bf16.f32 "
        "{%0,%1,%2,%3}, {%4,%5,%6,%7}, {%8,%9}, {%0,%1,%2,%3};"
        : "+f"(d[0]),"+f"(d[1]),"+f"(d[2]),"+f"(d[3])
        : "r"(a[0]),"r"(a[1]),"r"(a[2]),"r"(a[3]), "r"(b[0]),"r"(b[1]));
}

// ================= bf16x3 mma.sync GEMM: C[M,Nn] = A[M,K] * W[K,Nn] =================
// A split (Ah,Al) [M,K] bf16 row-major; W transposed+split (Bh,Bl) [Nn,K] bf16 row-major.
// CTA tile 128x128, 8 warps (2m x 4n), warp tile 64x32. K-chunk 32, 2-stage cp.async.
// smem per stage: 4 tiles of 128 rows x 32 bf16, row stride 40 bf16 (80B).
#define KC      32
#define ROWSTR  80                      // bytes per smem row (32 bf16 + 8 pad)
#define TILEB   (128*ROWSTR)            // 10240 B per tile
#define STAGEB  (4*TILEB)               // 40960 B per stage
#define GSM     (2*STAGEB)              // 81920 B

__device__ __forceinline__ void g_load_chunk(uint32_t sbase, int stage, int tid,
        const __nv_bfloat16* a0, const __nv_bfloat16* a1,
        const __nv_bfloat16* b0, const __nv_bfloat16* b1, int K, int koff){
    uint32_t st = sbase + stage*STAGEB;
    #pragma unroll
    for (int t = 0; t < 4; t++){
        const __nv_bfloat16* src = (t==0? a0 : t==1? a1 : t==2? b0 : b1);
        uint32_t tb = st + t*TILEB;
        #pragma unroll
        for (int s = 0; s < 2; s++){
            int idx = tid + s*256;            // 0..511
            int row = idx >> 2, seg = idx & 3;
            const __nv_bfloat16* g = src + (size_t)row*K + koff + seg*8;
            CP16(tb + row*ROWSTR + seg*16, g);
        }
    }
}

template<int ACT>
__global__ void __launch_bounds__(256)
tgemm_k(const __nv_bfloat16* __restrict__ Ah, const __nv_bfloat16* __restrict__ Al,
        const __nv_bfloat16* __restrict__ Bh, const __nv_bfloat16* __restrict__ Bl,
        const float* __restrict__ bias, const float* __restrict__ resid,
        float* __restrict__ C, int Nn, int K){
    extern __shared__ char smc[];
    uint32_t sb = _s2u(smc);
    int tid = threadIdx.x, wid = tid>>5, lane = tid&31;
    int wm = wid>>2, wn = wid&3;                 // 2 x 4 warp grid
    int bm = blockIdx.y*128, bn = blockIdx.x*128;

    const __nv_bfloat16* a0 = Ah + (size_t)bm*K;
    const __nv_bfloat16* a1 = Al + (size_t)bm*K;
    const __nv_bfloat16* b0 = Bh + (size_t)bn*K;
    const __nv_bfloat16* b1 = Bl + (size_t)bn*K;
    int nk = K/KC;

    float acc[4][4][4];
    #pragma unroll
    for (int i = 0; i < 4; i++){
        #pragma unroll
        for (int j = 0; j < 4; j++){
            #pragma unroll
            for (int q = 0; q < 4; q++) acc[i][j][q] = 0.f;
        }
    }

    g_load_chunk(sb, 0, tid, a0,a1,b0,b1, K, 0);
    CPCOMMIT();
    g_load_chunk(sb, 1, tid, a0,a1,b0,b1, K, KC);
    CPCOMMIT();

    // per-lane fragment address components
    int arow = (lane & 15);                      // within m16 tile
    int akhi = (lane >> 4) * 8;                  // k offset 0/8
    int brow = (lane & 7);                       // within n8 tile
    int bkhi = ((lane >> 3) & 1) * 8;

    for (int c = 0; c < nk; c++){
        if (c+1 < nk) { CPWAITG(1); } else { CPWAITG(0); }
        __syncthreads();
        uint32_t st = sb + (c&1)*STAGEB;
        uint32_t Abase = st + (wm*64 + arow)*ROWSTR;
        uint32_t Bbase = st + 2*TILEB + (wn*32 + brow)*ROWSTR;
        #pragma unroll
        for (int kk2 = 0; kk2 < 2; kk2++){
            int kca = (kk2*16 + akhi)*2;
            int kcb = (kk2*16 + bkhi)*2;
            uint32_t ah[4][4], al[4][4], bh[4][2], bl[4][2];
            #pragma unroll
            for (int mi = 0; mi < 4; mi++){
                uint32_t addr = Abase + mi*16*ROWSTR + kca;
                ldsm_x4(addr, ah[mi]);
                ldsm_x4(addr + TILEB, al[mi]);
            }
            #pragma unroll
            for (int ni = 0; ni < 4; ni++){
                uint32_t addr = Bbase + ni*8*ROWSTR + kcb;
                ldsm_x2(addr, bh[ni]);
                ldsm_x2(addr + TILEB, bl[ni]);
            }
            #pragma unroll
            for (int mi = 0; mi < 4; mi++){
                #pragma unroll
                for (int ni = 0; ni < 4; ni++){
                    mma16816(acc[mi][ni], ah[mi], bh[ni]);
                    mma16816(acc[mi][ni], ah[mi], bl[ni]);
                    mma16816(acc[mi][ni], al[mi], bh[ni]);
                }
            }
        }
        __syncthreads();
        if (c+2 < nk){
            g_load_chunk(sb, c&1, tid, a0,a1,b0,b1, K, (c+2)*KC);
            CPCOMMIT();
        }
    }

    // epilogue: acc layout c0,c1 -> (row=lane/4, col=2*(lane%4)+{0,1}); c2,c3 -> row+8
    int r_in = lane >> 2, c_in = (lane & 3)*2;
    #pragma unroll
    for (int mi = 0; mi < 4; mi++){
        #pragma unroll
        for (int ni = 0; ni < 4; ni++){
            int gr = bm + wm*64 + mi*16 + r_in;
            int gc = bn + wn*32 + ni*8 + c_in;
            float b0v = bias ? bias[gc]   : 0.f;
            float b1v = bias ? bias[gc+1] : 0.f;
            #pragma unroll
            for (int half = 0; half < 2; half++){
                int rr = gr + half*8;
                float v0 = acc[mi][ni][half*2+0] + b0v;
                float v1 = acc[mi][ni][half*2+1] + b1v;
                if (ACT == 1){
                    float u = v0; v0 = 0.5f*u*(1.f+tanhf(0.7978845608028654f*(u+0.044715f*u*u*u)));
                    u = v1;       v1 = 0.5f*u*(1.f+tanhf(0.7978845608028654f*(u+0.044715f*u*u*u)));
                }
                if (ACT == 2){ v0 *= 0.5f; v1 *= 0.5f; }
                if (resid){
                    v0 += resid[(size_t)rr*Nn + gc];
                    v1 += resid[(size_t)rr*Nn + gc + 1];
                }
                float2 o; o.x = v0; o.y = v1;
                *(float2*)&C[(size_t)rr*Nn + gc] = o;
            }
        }
    }
}

// ---------------- split fp32 -> bf16 hi/lo ----------------
__global__ void split_bf16_k(const float* __restrict__ x, __nv_bfloat16* __restrict__ hi,
                             __nv_bfloat16* __restrict__ lo, int n){
    int i = blockIdx.x*blockDim.x + threadIdx.x;
    if (i >= n) return;
    float v = x[i];
    __nv_bfloat16 h = __float2bfloat16(v);
    float r = v - __bfloat162float(h);
    hi[i] = h; lo[i] = __float2bfloat16(r);
}

// ---------------- transpose + split weights: W[K,N] -> Wt hi/lo [N,K] ----------------
__global__ void tsplit_k(const float* __restrict__ W, __nv_bfloat16* __restrict__ hi,
                         __nv_bfloat16* __restrict__ lo, int K, int N){
    __shared__ float tile[32][33];
    int bn = blockIdx.x*32, bk = blockIdx.y*32;
    int tx = threadIdx.x, ty = threadIdx.y;   // (32,8)
    for (int i=ty;i<32;i+=8) tile[i][tx] = W[(size_t)(bk+i)*N + bn+tx];
    __syncthreads();
    for (int i=ty;i<32;i+=8){
        float v = tile[tx][i];                 // = W[bk+tx][bn+i]
        __nv_bfloat16 h = __float2bfloat16(v);
        float r = v - __bfloat162float(h);
        size_t o = (size_t)(bn+i)*K + bk+tx;
        hi[o]=h; lo[o]=__float2bfloat16(r);
    }
}

// ---------------- rope table (double precision, computed once per launch) ----------------
__global__ void rope_table_k(float* __restrict__ sins, float* __restrict__ coss){
    int idx = blockIdx.x*blockDim.x + threadIdx.x;
    if (idx >= KVL*32) return;
    int p = idx>>5, lane = idx&31;
    double inv = exp(-(double)lane * 0.28782313662425575);   // ln(10000)/32
    double sd, cd; sincos((double)p*inv, &sd, &cd);
    sins[idx]=(float)sd; coss[idx]=(float)cd;
}

// ---------------- rmsnorm: one block per row ----------------
__global__ void rmsnorm_k(const float* __restrict__ x, const float* __restrict__ w,
                          float* __restrict__ y) {
    int r = blockIdx.x, tid = threadIdx.x;
    const float* xr = x + (size_t)r*DM;
    float ss = 0.f;
    for (int i = tid; i < DM; i += 256) { float v = xr[i]; ss += v*v; }
    __shared__ float red[256];
    red[tid] = ss; __syncthreads();
    for (int s = 128; s > 0; s >>= 1) { if (tid < s) red[tid] += red[tid+s]; __syncthreads(); }
    float rs = rsqrtf(red[0] * (1.f/DM) + EPS);
    float* yr = y + (size_t)r*DM;
    for (int i = tid; i < DM; i += 256) yr[i] = xr[i]*rs*w[i];
}

// ---------------- kv cache copy ----------------
__global__ void copy_cache_k(const float* __restrict__ cached, float* __restrict__ kvout) {
    int idx = blockIdx.x*blockDim.x + threadIdx.x;
    const int per = CCH*2*NH*HD;
    const int tot = BB*per;
    if (idx >= tot) return;
    int b = idx / per, r = idx % per;
    kvout[(size_t)b*KVL*2*NH*HD + r] = cached[idx];
}

// ---------------- qkv post: per-head rmsnorm, write K/V to cache, rope Q ----------------
__global__ void qkv_post_k(const float* __restrict__ qkv, const float* __restrict__ qw,
                           const float* __restrict__ kw, float* __restrict__ kvout,
                           float* __restrict__ qrot,
                           const float* __restrict__ rs_, const float* __restrict__ rc_) {
    int w = (blockIdx.x*blockDim.x + threadIdx.x) >> 5;
    int lane = threadIdx.x & 31;
    if (w >= RR*NH) return;
    int b = w / (NN*NH), rem = w % (NN*NH);
    int n = rem / NH, h = rem % NH;
    const float* base = qkv + (size_t)(b*NN + n)*(3*NH*HD) + h*HD*3;
    float q0 = base[lane*3+0],      q1 = base[(lane+32)*3+0];
    float k0 = base[lane*3+1],      k1 = base[(lane+32)*3+1];
    float v0 = base[lane*3+2],      v1 = base[(lane+32)*3+2];
    float ssq = q0*q0 + q1*q1, ssk = k0*k0 + k1*k1;
    #pragma unroll
    for (int off = 16; off; off >>= 1) {
        ssq += __shfl_xor_sync(0xffffffffu, ssq, off);
        ssk += __shfl_xor_sync(0xffffffffu, ssk, off);
    }
    float rq = rsqrtf(ssq*(1.f/HD) + EPS);
    float rk = rsqrtf(ssk*(1.f/HD) + EPS);
    q0 *= rq*qw[lane]; q1 *= rq*qw[lane+32];
    k0 *= rk*kw[lane]; k1 *= rk*kw[lane+32];
    size_t ko = ((((size_t)b*KVL + CCH + n)*2 + 0)*NH + h)*HD;
    kvout[ko + lane] = k0;            kvout[ko + lane + 32] = k1;
    size_t vo = ko + (size_t)NH*HD;
    kvout[vo + lane] = v0;            kvout[vo + lane + 32] = v1;
    int ti = (CCH + n)*32 + lane;
    float s = rs_[ti], c = rc_[ti];
    size_t qo = ((size_t)(b*NN + n)*NH + h)*HD;
    qrot[qo + lane]      = q0*c - q1*s;
    qrot[qo + lane + 32] = q1*c + q0*s;
}

// ---------------- rope over the full K cache ----------------
__global__ void rope_k_k(const float* __restrict__ kvout, float* __restrict__ krot,
                         const float* __restrict__ rs_, const float* __restrict__ rc_) {
    int w = (blockIdx.x*blockDim.x + threadIdx.x) >> 5;
    int lane = threadIdx.x & 31;
    if (w >= BB*KVL*NH) return;
    int b = w / (KVL*NH), rem = w % (KVL*NH);
    int p = rem / NH, h = rem % NH;
    size_t ko = ((((size_t)b*KVL + p)*2 + 0)*NH + h)*HD;
    float k0 = kvout[ko + lane], k1 = kvout[ko + lane + 32];
    int ti = p*32 + lane;
    float s = rs_[ti], c = rc_[ti];
    size_t o = ((size_t)(b*KVL + p)*NH + h)*HD;
    krot[o + lane]      = k0*c - k1*s;
    krot[o + lane + 32] = k1*c + k0*s;
}

// ---------------- flash attention: block per (b,h,64-query tile) ----------------
#define BQ   64
#define BK   64
#define APAD 65
__global__ void flash_attn_k(const float* __restrict__ qrot, const float* __restrict__ krot,
                             const float* __restrict__ kvout, float* __restrict__ out) {
    extern __shared__ float sm[];
    float* Qs = sm;
    float* Ks = Qs + BQ*APAD;
    float* Vs = Ks + BK*APAD;
    float* Ps = Vs + BK*APAD;
    int qt = blockIdx.x, h = blockIdx.y, b = blockIdx.z;
    int t = threadIdx.x;
    int ty = t >> 3, tx = t & 7;

    for (int idx = t; idx < BQ*16; idx += 128) {
        int r = idx >> 4, c4 = (idx & 15) * 4;
        int q = qt*BQ + r;
        float4 v = *(const float4*)&qrot[((size_t)(b*NN + q)*NH + h)*HD + c4];
        Qs[r*APAD + c4+0] = v.x * 0.125f;
        Qs[r*APAD + c4+1] = v.y * 0.125f;
        Qs[r*APAD + c4+2] = v.z * 0.125f;
        Qs[r*APAD + c4+3] = v.w * 0.125f;
    }

    float acc[4][8] = {};
    float m_r[4] = {-1e30f,-1e30f,-1e30f,-1e30f};
    float l_r[4] = {};

    for (int p0 = 0; p0 < KVL; p0 += BK) {
        __syncthreads();
        for (int idx = t; idx < BK*16; idx += 128) {
            int j = idx >> 4, c4 = (idx & 15) * 4;
            int p = p0 + j;
            float4 kv = *(const float4*)&krot[((size_t)(b*KVL + p)*NH + h)*HD + c4];
            Ks[j*APAD + c4+0] = kv.x; Ks[j*APAD + c4+1] = kv.y;
            Ks[j*APAD + c4+2] = kv.z; Ks[j*APAD + c4+3] = kv.w;
            float4 vv = *(const float4*)&kvout[(((size_t)(b*KVL + p)*2 + 1)*NH + h)*HD + c4];
            Vs[j*APAD + c4+0] = vv.x; Vs[j*APAD + c4+1] = vv.y;
            Vs[j*APAD + c4+2] = vv.z; Vs[j*APAD + c4+3] = vv.w;
        }
        __syncthreads();

        float s[4][8] = {};
        #pragma unroll 8
        for (int d = 0; d < HD; d++) {
            float qv[4], kv[8];
            #pragma unroll
            for (int i = 0; i < 4; i++) qv[i] = Qs[(ty*4+i)*APAD + d];
            #pragma unroll
            for (int jj = 0; jj < 8; jj++) kv[jj] = Ks[(tx*8+jj)*APAD + d];
            #pragma unroll
            for (int i = 0; i < 4; i++)
                #pragma unroll
                for (int jj = 0; jj < 8; jj++)
                    s[i][jj] += qv[i]*kv[jj];
        }

        #pragma unroll
        for (int i = 0; i < 4; i++) {
            float mx = s[i][0];
            #pragma unroll
            for (int jj = 1; jj < 8; jj++) mx = fmaxf(mx, s[i][jj]);
            #pragma unroll
            for (int off = 1; off < 8; off <<= 1)
                mx = fmaxf(mx, __shfl_xor_sync(0xffffffffu, mx, off));
            float mn = fmaxf(m_r[i], mx);
            float corr = __expf(m_r[i] - mn);
            m_r[i] = mn;
            float ls = 0.f;
            #pragma unroll
            for (int jj = 0; jj < 8; jj++) {
                float e = __expf(s[i][jj] - mn);
                Ps[(ty*4+i)*APAD + tx*8+jj] = e;
                ls += e;
            }
            #pragma unroll
            for (int off = 1; off < 8; off <<= 1)
                ls += __shfl_xor_sync(0xffffffffu, ls, off);
            l_r[i] = l_r[i]*corr + ls;
            #pragma unroll
            for (int dd = 0; dd < 8; dd++) acc[i][dd] *= corr;
        }
        __syncthreads();

        #pragma unroll 8
        for (int j = 0; j < BK; j++) {
            float pv[4], vv[8];
            #pragma unroll
            for (int i = 0; i < 4; i++) pv[i] = Ps[(ty*4+i)*APAD + j];
            #pragma unroll
            for (int dd = 0; dd < 8; dd++) vv[dd] = Vs[j*APAD + tx*8+dd];
            #pragma unroll
            for (int i = 0; i < 4; i++)
                #pragma unroll
                for (int dd = 0; dd < 8; dd++)
                    acc[i][dd] += pv[i]*vv[dd];
        }
    }

    #pragma unroll
    for (int i = 0; i < 4; i++) {
        float rl = 1.f / l_r[i];
        int q = qt*BQ + ty*4 + i;
        size_t o = ((size_t)(b*NN + q)*NH + h)*HD + tx*8;
        #pragma unroll
        for (int dd = 0; dd < 8; dd++) out[o + dd] = acc[i][dd]*rl;
    }
}

// ---------------- GLU ----------------
__global__ void glu_k(const float* __restrict__ in, float* __restrict__ out) {
    int idx = blockIdx.x*blockDim.x + threadIdx.x;
    if (idx >= RR*DM) return;
    int r = idx / DM, c = idx % DM;
    float a = in[(size_t)r*(2*DM) + c];
    float g = in[(size_t)r*(2*DM) + DM + c];
    out[idx] = a / (1.f + expf(-g));
}

// ---------------- depthwise conv ----------------
__global__ void dwconv_k(const float* __restrict__ in, const float* __restrict__ w,
                         const float* __restrict__ bias, float* __restrict__ out) {
    int idx = blockIdx.x*blockDim.x + threadIdx.x;
    if (idx >= RR*DM) return;
    int c = idx % DM, bn = idx / DM;
    int n = bn % NN, b = bn / NN;
    const float* wr = w + c*KSZ;
    const float* base = in + (size_t)b*NN*DM + c;
    float acc = bias[c];
    #pragma unroll
    for (int t = 0; t < KSZ; t++) {
        int nn = n + t - (KSZ/2);
        if (nn >= 0 && nn < NN) acc += base[(size_t)nn*DM] * wr[t];
    }
    out[idx] = acc;
}

// ---------------- batchnorm stats ----------------
__global__ void bnstats_k(const float* __restrict__ x, float* __restrict__ mean,
                          float* __restrict__ var) {
    int c = blockIdx.x, tid = threadIdx.x;
    float s = 0.f, s2 = 0.f;
    for (int r = tid; r < RR; r += 256) {
        float v = x[(size_t)r*DM + c];
        s += v; s2 += v*v;
    }
    __shared__ float rs[256], rs2[256];
    rs[tid] = s; rs2[tid] = s2; __syncthreads();
    for (int k = 128; k > 0; k >>= 1) {
        if (tid < k) { rs[tid] += rs[tid+k]; rs2[tid] += rs2[tid+k]; }
        __syncthreads();
    }
    if (tid == 0) {
        float m = rs[0] * (1.f/RR);
        mean[c] = m;
        var[c] = rs2[0] * (1.f/RR) - m*m;
    }
}

// ---------------- batchnorm apply + swish ----------------
__global__ void bnapply_k(const float* __restrict__ x, const float* __restrict__ mean,
                          const float* __restrict__ var, const float* __restrict__ g,
                          const float* __restrict__ b, float* __restrict__ out) {
    int idx = blockIdx.x*blockDim.x + threadIdx.x;
    if (idx >= RR*DM) return;
    int c = idx % DM;
    float v = (x[idx] - mean[c]) * rsqrtf(var[c] + EPS) * g[c] + b[c];
    out[idx] = v / (1.f + expf(-v));
}

// ---------------- launch ----------------
extern "C" void kernel_launch(void* const* d_in, const int* in_sizes, int n_in,
                              void* d_out, int out_size) {
    const float* x_in      = (const float*)d_in[0];
    const float* cached    = (const float*)d_in[4];
    const float* ff1_nw    = (const float*)d_in[5];
    const float* ff1_w1    = (const float*)d_in[6];
    const float* ff1_b1    = (const float*)d_in[7];
    const float* ff1_w2    = (const float*)d_in[8];
    const float* ff1_b2    = (const float*)d_in[9];
    const float* attn_nw   = (const float*)d_in[10];
    const float* qkv_w     = (const float*)d_in[11];
    const float* out_w     = (const float*)d_in[12];
    const float* q_nw      = (const float*)d_in[13];
    const float* k_nw      = (const float*)d_in[14];
    const float* conv_nw   = (const float*)d_in[15];
    const float* pw1_w     = (const float*)d_in[16];
    const float* pw1_b     = (const float*)d_in[17];
    const float* dw_w      = (const float*)d_in[18];
    const float* dw_b      = (const float*)d_in[19];
    const float* bn_g      = (const float*)d_in[20];
    const float* bn_b      = (const float*)d_in[21];
    const float* pw2_w     = (const float*)d_in[22];
    const float* pw2_b     = (const float*)d_in[23];
    const float* ff2_nw    = (const float*)d_in[24];
    const float* ff2_w1    = (const float*)d_in[25];
    const float* ff2_b1    = (const float*)d_in[26];
    const float* ff2_w2    = (const float*)d_in[27];
    const float* ff2_b2    = (const float*)d_in[28];
    const float* out_nw    = (const float*)d_in[29];

    float* outx  = (float*)d_out;
    float* kvout = outx + (size_t)RR*DM;

    float *x_, *norm_, *ff_, *qkv_, *qrot_, *krot_, *attn_, *glu_, *dw_, *mean_, *var_, *rs_, *rc_;
    __nv_bfloat16 *wth_, *wtl_, *abh_, *abl_;
    cudaGetSymbolAddress((void**)&x_,    g_x);
    cudaGetSymbolAddress((void**)&norm_, g_norm);
    cudaGetSymbolAddress((void**)&ff_,   g_ff);
    cudaGetSymbolAddress((void**)&qkv_,  g_qkv);
    cudaGetSymbolAddress((void**)&qrot_, g_qrot);
    cudaGetSymbolAddress((void**)&krot_, g_krot);
    cudaGetSymbolAddress((void**)&attn_, g_attn);
    cudaGetSymbolAddress((void**)&glu_,  g_glu);
    cudaGetSymbolAddress((void**)&dw_,   g_dw);
    cudaGetSymbolAddress((void**)&mean_, g_mean);
    cudaGetSymbolAddress((void**)&var_,  g_var);
    cudaGetSymbolAddress((void**)&rs_,   g_rs);
    cudaGetSymbolAddress((void**)&rc_,   g_rc);
    cudaGetSymbolAddress((void**)&wth_,  g_wth);
    cudaGetSymbolAddress((void**)&wtl_,  g_wtl);
    cudaGetSymbolAddress((void**)&abh_,  g_abh);
    cudaGetSymbolAddress((void**)&abl_,  g_abl);

    static int attr_set = 0;
    if (!attr_set) {
        cudaFuncSetAttribute(flash_attn_k, cudaFuncAttributeMaxDynamicSharedMemorySize,
                             4*BQ*APAD*sizeof(float));
        cudaFuncSetAttribute(tgemm_k<0>, cudaFuncAttributeMaxDynamicSharedMemorySize, GSM);
        cudaFuncSetAttribute(tgemm_k<1>, cudaFuncAttributeMaxDynamicSharedMemorySize, GSM);
        cudaFuncSetAttribute(tgemm_k<2>, cudaFuncAttributeMaxDynamicSharedMemorySize, GSM);
        attr_set = 1;
    }

    // weight offsets (transposed [N,K] layouts)
    size_t o = 0;
    size_t off_qkv = o; o += (size_t)(3*NH*HD)*DM;
    size_t off_out = o; o += (size_t)DM*DM;
    size_t off_f1a = o; o += (size_t)FF*DM;
    size_t off_f1b = o; o += (size_t)DM*FF;
    size_t off_pw1 = o; o += (size_t)(2*DM)*DM;
    size_t off_pw2 = o; o += (size_t)DM*DM;
    size_t off_f2a = o; o += (size_t)FF*DM;
    size_t off_f2b = o; o += (size_t)DM*FF;

    dim3 tb(32,8);
    tsplit_k<<<dim3((3*NH*HD)/32, DM/32), tb>>>(qkv_w,  wth_+off_qkv, wtl_+off_qkv, DM, 3*NH*HD);
    tsplit_k<<<dim3(DM/32, DM/32),        tb>>>(out_w,  wth_+off_out, wtl_+off_out, DM, DM);
    tsplit_k<<<dim3(FF/32, DM/32),        tb>>>(ff1_w1, wth_+off_f1a, wtl_+off_f1a, DM, FF);
    tsplit_k<<<dim3(DM/32, FF/32),        tb>>>(ff1_w2, wth_+off_f1b, wtl_+off_f1b, FF, DM);
    tsplit_k<<<dim3((2*DM)/32, DM/32),    tb>>>(pw1_w,  wth_+off_pw1, wtl_+off_pw1, DM, 2*DM);
    tsplit_k<<<dim3(DM/32, DM/32),        tb>>>(pw2_w,  wth_+off_pw2, wtl_+off_pw2, DM, DM);
    tsplit_k<<<dim3(FF/32, DM/32),        tb>>>(ff2_w1, wth_+off_f2a, wtl_+off_f2a, DM, FF);
    tsplit_k<<<dim3(DM/32, FF/32),        tb>>>(ff2_w2, wth_+off_f2b, wtl_+off_f2b, FF, DM);
    rope_table_k<<<(KVL*32 + 255)/256, 256>>>(rs_, rc_);

    cudaMemcpyAsync(x_, x_in, sizeof(float)*(size_t)RR*DM, cudaMemcpyDeviceToDevice, 0);

    const int EW = (RR*DM + 255)/256;
    const int SW_DM = (RR*DM + 255)/256, SW_FF = (RR*FF + 255)/256;

    // ---- FF1
    rmsnorm_k<<<RR, 256>>>(x_, ff1_nw, norm_);
    split_bf16_k<<<SW_DM, 256>>>(norm_, abh_, abl_, RR*DM);
    tgemm_k<1><<<dim3(FF/128, RR/128), 256, GSM>>>(abh_, abl_, wth_+off_f1a, wtl_+off_f1a,
                                                   ff1_b1, nullptr, ff_, FF, DM);
    split_bf16_k<<<SW_FF, 256>>>(ff_, abh_, abl_, RR*FF);
    tgemm_k<2><<<dim3(DM/128, RR/128), 256, GSM>>>(abh_, abl_, wth_+off_f1b, wtl_+off_f1b,
                                                   ff1_b2, x_, x_, DM, FF);

    // ---- Attention
    rmsnorm_k<<<RR, 256>>>(x_, attn_nw, norm_);
    split_bf16_k<<<SW_DM, 256>>>(norm_, abh_, abl_, RR*DM);
    tgemm_k<0><<<dim3((3*NH*HD)/128, RR/128), 256, GSM>>>(abh_, abl_, wth_+off_qkv, wtl_+off_qkv,
                                                          nullptr, nullptr, qkv_, 3*NH*HD, DM);
    copy_cache_k<<<(BB*CCH*2*NH*HD + 255)/256, 256>>>(cached, kvout);
    qkv_post_k<<<RR*NH/4, 128>>>(qkv_, q_nw, k_nw, kvout, qrot_, rs_, rc_);
    rope_k_k<<<BB*KVL*NH/4, 128>>>(kvout, krot_, rs_, rc_);
    flash_attn_k<<<dim3(NN/BQ, NH, BB), 128, 4*BQ*APAD*sizeof(float)>>>(qrot_, krot_, kvout, attn_);
    split_bf16_k<<<SW_DM, 256>>>(attn_, abh_, abl_, RR*DM);
    tgemm_k<0><<<dim3(DM/128, RR/128), 256, GSM>>>(abh_, abl_, wth_+off_out, wtl_+off_out,
                                                   nullptr, x_, x_, DM, DM);

    // ---- Conv module
    rmsnorm_k<<<RR, 256>>>(x_, conv_nw, norm_);
    split_bf16_k<<<SW_DM, 256>>>(norm_, abh_, abl_, RR*DM);
    tgemm_k<0><<<dim3((2*DM)/128, RR/128), 256, GSM>>>(abh_, abl_, wth_+off_pw1, wtl_+off_pw1,
                                                       pw1_b, nullptr, ff_, 2*DM, DM);
    glu_k<<<EW, 256>>>(ff_, glu_);
    dwconv_k<<<EW, 256>>>(glu_, dw_w, dw_b, dw_);
    bnstats_k<<<DM, 256>>>(dw_, mean_, var_);
    bnapply_k<<<EW, 256>>>(dw_, mean_, var_, bn_g, bn_b, glu_);
    split_bf16_k<<<SW_DM, 256>>>(glu_, abh_, abl_, RR*DM);
    tgemm_k<0><<<dim3(DM/128, RR/128), 256, GSM>>>(abh_, abl_, wth_+off_pw2, wtl_+off_pw2,
                                                   pw2_b, nullptr, x_, DM, DM);

    // ---- FF2
    rmsnorm_k<<<RR, 256>>>(x_, ff2_nw, norm_);
    split_bf16_k<<<SW_DM, 256>>>(norm_, abh_, abl_, RR*DM);
    tgemm_k<1><<<dim3(FF/128, RR/128), 256, GSM>>>(abh_, abl_, wth_+off_f2a, wtl_+off_f2a,
                                                   ff2_b1, nullptr, ff_, FF, DM);
    split_bf16_k<<<SW_FF, 256>>>(ff_, abh_, abl_, RR*FF);
    tgemm_k<2><<<dim3(DM/128, RR/128), 256, GSM>>>(abh_, abl_, wth_+off_f2b, wtl_+off_f2b,
                                                   ff2_b2, x_, x_, DM, FF);

    // ---- final rmsnorm -> output x
    rmsnorm_k<<<RR, 256>>>(x_, out_nw, outx);
}

// round 12
// speedup vs baseline: 2.6344x; 1.5244x over previous
#include <cuda_runtime.h>
#include <cuda_bf16.h>
#include <math.h>
#include <stdint.h>

// ---------------- problem constants ----------------
#define BB    2
#define NN    2048
#define CCH   512
#define KVL   2560          // CCH + NN
#define DM    768
#define NH    12
#define HD    64
#define FF    3072
#define KSZ   31
#define RR    (BB*NN)       // 4096 token rows
#define EPS   1e-5f

// ---------------- scratch (static device memory; no allocs) ----------------
__device__ float g_x   [RR*DM];
__device__ float g_ff  [RR*FF];          // fp32 GEMM outputs (pw1)
__device__ float g_qkv [RR*3*NH*HD];
__device__ float g_glu [RR*DM];
__device__ float g_dw  [RR*DM];
__device__ float g_mean[DM];
__device__ float g_var [DM];
__device__ float g_rs  [KVL*32];         // rope sin table
__device__ float g_rc  [KVL*32];         // rope cos table

#define WT_TOTAL 13565952
__device__ __align__(256) __nv_bfloat16 g_wth[WT_TOTAL];   // transposed weights hi
__device__ __align__(256) __nv_bfloat16 g_wtl[WT_TOTAL];   // transposed weights lo
__device__ __align__(256) __nv_bfloat16 g_abh[RR*FF];      // FF-wide activation hi
__device__ __align__(256) __nv_bfloat16 g_abl[RR*FF];      // FF-wide activation lo
__device__ __align__(256) __nv_bfloat16 g_a1h[RR*DM];      // DM-wide activation hi
__device__ __align__(256) __nv_bfloat16 g_a1l[RR*DM];      // DM-wide activation lo
__device__ __align__(256) __nv_bfloat16 g_qsh[RR*DM];      // Q split hi  [b,h,n,d] (scaled)
__device__ __align__(256) __nv_bfloat16 g_qsl[RR*DM];
#define KVE (BB*NH*KVL*HD)
__device__ __align__(256) __nv_bfloat16 g_ksh[KVE];        // roped K hi [b,h,p,d]
__device__ __align__(256) __nv_bfloat16 g_ksl[KVE];
__device__ __align__(256) __nv_bfloat16 g_vsh[KVE];        // V hi [b,h,p,d]
__device__ __align__(256) __nv_bfloat16 g_vsl[KVE];

// ================= PTX helpers (base sm_103-safe) ====
__device__ __forceinline__ uint32_t _s2u(const void* p){
    uint32_t a; asm("{ .reg .u64 t; cvta.to.shared.u64 t, %1; cvt.u32.u64 %0, t; }":"=r"(a):"l"(p)); return a;
}
#define CP16(d,s)   asm volatile("cp.async.cg.shared.global [%0], [%1], 16;"::"r"(d),"l"(s):"memory")
#define CPCOMMIT()  asm volatile("cp.async.commit_group;":::"memory")
#define CPWAITG(n)  asm volatile("cp.async.wait_group %0;"::"n"(n):"memory")

__device__ __forceinline__ void ldsm_x4(uint32_t a, uint32_t r[4]){
    asm volatile("ldmatrix.sync.aligned.m8n8.x4.shared.b16 {%0,%1,%2,%3}, [%4];"
        : "=r"(r[0]),"=r"(r[1]),"=r"(r[2]),"=r"(r[3]) : "r"(a));
}
__device__ __forceinline__ void ldsm_x2(uint32_t a, uint32_t r[2]){
    asm volatile("ldmatrix.sync.aligned.m8n8.x2.shared.b16 {%0,%1}, [%2];"
        : "=r"(r[0]),"=r"(r[1]) : "r"(a));
}
__device__ __forceinline__ void ldsm_x2t(uint32_t a, uint32_t r[2]){
    asm volatile("ldmatrix.sync.aligned.m8n8.x2.trans.shared.b16 {%0,%1}, [%2];"
        : "=r"(r[0]),"=r"(r[1]) : "r"(a));
}
__device__ __forceinline__ void mma16816(float d[4], const uint32_t a[4], const uint32_t b[2]){
    asm volatile("mma.sync.aligned.m16n8k16.row.col.f32.bf16.bf16.f32 "
        "{%0,%1,%2,%3}, {%4,%5,%6,%7}, {%8,%9}, {%0,%1,%2,%3};"
        : "+f"(d[0]),"+f"(d[1]),"+f"(d[2]),"+f"(d[3])
        : "r"(a[0]),"r"(a[1]),"r"(a[2]),"r"(a[3]), "r"(b[0]),"r"(b[1]));
}

__device__ __forceinline__ void split2(float v, __nv_bfloat16& h, __nv_bfloat16& l){
    h = __float2bfloat16(v);
    l = __float2bfloat16(v - __bfloat162float(h));
}
// pack two floats into bf16x2 hi and lo (residual) words; low 16 bits = first arg
__device__ __forceinline__ void pack_hl(float p0, float p1, uint32_t& hi, uint32_t& lo){
    __nv_bfloat162 th, tl;
    th.x = __float2bfloat16(p0); th.y = __float2bfloat16(p1);
    tl.x = __float2bfloat16(p0 - __bfloat162float(th.x));
    tl.y = __float2bfloat16(p1 - __bfloat162float(th.y));
    hi = *reinterpret_cast<uint32_t*>(&th);
    lo = *reinterpret_cast<uint32_t*>(&tl);
}

// ================= bf16x3 mma.sync GEMM =================
#define KC      32
#define ROWSTR  80
#define TILEB   (128*ROWSTR)
#define STAGEB  (4*TILEB)
#define GSM     (2*STAGEB)

__device__ __forceinline__ void g_load_chunk(uint32_t sbase, int stage, int tid,
        const __nv_bfloat16* a0, const __nv_bfloat16* a1,
        const __nv_bfloat16* b0, const __nv_bfloat16* b1, int K, int koff){
    uint32_t st = sbase + stage*STAGEB;
    #pragma unroll
    for (int t = 0; t < 4; t++){
        const __nv_bfloat16* src = (t==0? a0 : t==1? a1 : t==2? b0 : b1);
        uint32_t tb = st + t*TILEB;
        #pragma unroll
        for (int s = 0; s < 2; s++){
            int idx = tid + s*256;
            int row = idx >> 2, seg = idx & 3;
            const __nv_bfloat16* g = src + (size_t)row*K + koff + seg*8;
            CP16(tb + row*ROWSTR + seg*16, g);
        }
    }
}

template<int ACT, int OUTB>
__global__ void __launch_bounds__(256)
tgemm_k(const __nv_bfloat16* __restrict__ Ah, const __nv_bfloat16* __restrict__ Al,
        const __nv_bfloat16* __restrict__ Bh, const __nv_bfloat16* __restrict__ Bl,
        const float* __restrict__ bias, const float* __restrict__ resid,
        float* __restrict__ C, __nv_bfloat16* __restrict__ Ch, __nv_bfloat16* __restrict__ Cl,
        int Nn, int K){
    extern __shared__ char smc[];
    uint32_t sb = _s2u(smc);
    int tid = threadIdx.x, wid = tid>>5, lane = tid&31;
    int wm = wid>>2, wn = wid&3;
    int bm = blockIdx.y*128, bn = blockIdx.x*128;

    const __nv_bfloat16* a0 = Ah + (size_t)bm*K;
    const __nv_bfloat16* a1 = Al + (size_t)bm*K;
    const __nv_bfloat16* b0 = Bh + (size_t)bn*K;
    const __nv_bfloat16* b1 = Bl + (size_t)bn*K;
    int nk = K/KC;

    float acc[4][4][4];
    #pragma unroll
    for (int i = 0; i < 4; i++){
        #pragma unroll
        for (int j = 0; j < 4; j++){
            #pragma unroll
            for (int q = 0; q < 4; q++) acc[i][j][q] = 0.f;
        }
    }

    g_load_chunk(sb, 0, tid, a0,a1,b0,b1, K, 0);
    CPCOMMIT();
    g_load_chunk(sb, 1, tid, a0,a1,b0,b1, K, KC);
    CPCOMMIT();

    int arow = (lane & 15);
    int akhi = (lane >> 4) * 8;
    int brow = (lane & 7);
    int bkhi = ((lane >> 3) & 1) * 8;

    for (int c = 0; c < nk; c++){
        if (c+1 < nk) { CPWAITG(1); } else { CPWAITG(0); }
        __syncthreads();
        uint32_t st = sb + (c&1)*STAGEB;
        uint32_t Abase = st + (wm*64 + arow)*ROWSTR;
        uint32_t Bbase = st + 2*TILEB + (wn*32 + brow)*ROWSTR;
        #pragma unroll
        for (int kk2 = 0; kk2 < 2; kk2++){
            int kca = (kk2*16 + akhi)*2;
            int kcb = (kk2*16 + bkhi)*2;
            uint32_t ah[4][4], al[4][4], bh[4][2], bl[4][2];
            #pragma unroll
            for (int mi = 0; mi < 4; mi++){
                uint32_t addr = Abase + mi*16*ROWSTR + kca;
                ldsm_x4(addr, ah[mi]);
                ldsm_x4(addr + TILEB, al[mi]);
            }
            #pragma unroll
            for (int ni = 0; ni < 4; ni++){
                uint32_t addr = Bbase + ni*8*ROWSTR + kcb;
                ldsm_x2(addr, bh[ni]);
                ldsm_x2(addr + TILEB, bl[ni]);
            }
            #pragma unroll
            for (int mi = 0; mi < 4; mi++){
                #pragma unroll
                for (int ni = 0; ni < 4; ni++){
                    mma16816(acc[mi][ni], ah[mi], bh[ni]);
                    mma16816(acc[mi][ni], ah[mi], bl[ni]);
                    mma16816(acc[mi][ni], al[mi], bh[ni]);
                }
            }
        }
        __syncthreads();
        if (c+2 < nk){
            g_load_chunk(sb, c&1, tid, a0,a1,b0,b1, K, (c+2)*KC);
            CPCOMMIT();
        }
    }

    int r_in = lane >> 2, c_in = (lane & 3)*2;
    #pragma unroll
    for (int mi = 0; mi < 4; mi++){
        #pragma unroll
        for (int ni = 0; ni < 4; ni++){
            int gr = bm + wm*64 + mi*16 + r_in;
            int gc = bn + wn*32 + ni*8 + c_in;
            float b0v = bias ? bias[gc]   : 0.f;
            float b1v = bias ? bias[gc+1] : 0.f;
            #pragma unroll
            for (int half = 0; half < 2; half++){
                int rr = gr + half*8;
                float v0 = acc[mi][ni][half*2+0] + b0v;
                float v1 = acc[mi][ni][half*2+1] + b1v;
                if (ACT == 1){
                    float u = v0; v0 = 0.5f*u*(1.f+tanhf(0.7978845608028654f*(u+0.044715f*u*u*u)));
                    u = v1;       v1 = 0.5f*u*(1.f+tanhf(0.7978845608028654f*(u+0.044715f*u*u*u)));
                }
                if (ACT == 2){ v0 *= 0.5f; v1 *= 0.5f; }
                if (resid){
                    v0 += resid[(size_t)rr*Nn + gc];
                    v1 += resid[(size_t)rr*Nn + gc + 1];
                }
                if (OUTB){
                    uint32_t hw, lw;
                    pack_hl(v0, v1, hw, lw);
                    *reinterpret_cast<uint32_t*>(&Ch[(size_t)rr*Nn + gc]) = hw;
                    *reinterpret_cast<uint32_t*>(&Cl[(size_t)rr*Nn + gc]) = lw;
                } else {
                    float2 o; o.x = v0; o.y = v1;
                    *(float2*)&C[(size_t)rr*Nn + gc] = o;
                }
            }
        }
    }
}

// ---------------- transpose + split weights: W[K,N] -> Wt hi/lo [N,K] ----------------
__global__ void tsplit_k(const float* __restrict__ W, __nv_bfloat16* __restrict__ hi,
                         __nv_bfloat16* __restrict__ lo, int K, int N){
    __shared__ float tile[32][33];
    int bn = blockIdx.x*32, bk = blockIdx.y*32;
    int tx = threadIdx.x, ty = threadIdx.y;
    for (int i=ty;i<32;i+=8) tile[i][tx] = W[(size_t)(bk+i)*N + bn+tx];
    __syncthreads();
    for (int i=ty;i<32;i+=8){
        float v = tile[tx][i];
        __nv_bfloat16 h, l; split2(v, h, l);
        size_t o = (size_t)(bn+i)*K + bk+tx;
        hi[o]=h; lo[o]=l;
    }
}

// ---------------- rope table ----------------
__global__ void rope_table_k(float* __restrict__ sins, float* __restrict__ coss){
    int idx = blockIdx.x*blockDim.x + threadIdx.x;
    if (idx >= KVL*32) return;
    int p = idx>>5, lane = idx&31;
    double inv = exp(-(double)lane * 0.28782313662425575);
    double sd, cd; sincos((double)p*inv, &sd, &cd);
    sins[idx]=(float)sd; coss[idx]=(float)cd;
}

// ---------------- rmsnorm -> bf16 hi/lo split ----------------
__global__ void rmsnorm_split_k(const float* __restrict__ x, const float* __restrict__ w,
                                __nv_bfloat16* __restrict__ hi, __nv_bfloat16* __restrict__ lo) {
    int r = blockIdx.x, tid = threadIdx.x;
    const float* xr = x + (size_t)r*DM;
    float ss = 0.f;
    for (int i = tid; i < DM; i += 256) { float v = xr[i]; ss += v*v; }
    __shared__ float red[256];
    red[tid] = ss; __syncthreads();
    for (int s = 128; s > 0; s >>= 1) { if (tid < s) red[tid] += red[tid+s]; __syncthreads(); }
    float rs = rsqrtf(red[0] * (1.f/DM) + EPS);
    for (int i = tid; i < DM; i += 256){
        float v = xr[i]*rs*w[i];
        __nv_bfloat16 h, l; split2(v, h, l);
        hi[(size_t)r*DM + i] = h; lo[(size_t)r*DM + i] = l;
    }
}

// ---------------- plain rmsnorm (final) ----------------
__global__ void rmsnorm_k(const float* __restrict__ x, const float* __restrict__ w,
                          float* __restrict__ y) {
    int r = blockIdx.x, tid = threadIdx.x;
    const float* xr = x + (size_t)r*DM;
    float ss = 0.f;
    for (int i = tid; i < DM; i += 256) { float v = xr[i]; ss += v*v; }
    __shared__ float red[256];
    red[tid] = ss; __syncthreads();
    for (int s = 128; s > 0; s >>= 1) { if (tid < s) red[tid] += red[tid+s]; __syncthreads(); }
    float rs = rsqrtf(red[0] * (1.f/DM) + EPS);
    float* yr = y + (size_t)r*DM;
    for (int i = tid; i < DM; i += 256) yr[i] = xr[i]*rs*w[i];
}

// ---------------- kv cache copy ----------------
__global__ void copy_cache_k(const float* __restrict__ cached, float* __restrict__ kvout) {
    int idx = blockIdx.x*blockDim.x + threadIdx.x;
    const int per = CCH*2*NH*HD;
    const int tot = BB*per;
    if (idx >= tot) return;
    int b = idx / per, r = idx % per;
    kvout[(size_t)b*KVL*2*NH*HD + r] = cached[idx];
}

// ---------------- qkv post: head rmsnorm, K/V -> cache, rope+scale+split Q ----------------
__global__ void qkv_post_k(const float* __restrict__ qkv, const float* __restrict__ qw,
                           const float* __restrict__ kw, float* __restrict__ kvout,
                           __nv_bfloat16* __restrict__ qsh, __nv_bfloat16* __restrict__ qsl,
                           const float* __restrict__ rs_, const float* __restrict__ rc_) {
    int w = (blockIdx.x*blockDim.x + threadIdx.x) >> 5;
    int lane = threadIdx.x & 31;
    if (w >= RR*NH) return;
    int b = w / (NN*NH), rem = w % (NN*NH);
    int n = rem / NH, h = rem % NH;
    const float* base = qkv + (size_t)(b*NN + n)*(3*NH*HD) + h*HD*3;
    float q0 = base[lane*3+0],      q1 = base[(lane+32)*3+0];
    float k0 = base[lane*3+1],      k1 = base[(lane+32)*3+1];
    float v0 = base[lane*3+2],      v1 = base[(lane+32)*3+2];
    float ssq = q0*q0 + q1*q1, ssk = k0*k0 + k1*k1;
    #pragma unroll
    for (int off = 16; off; off >>= 1) {
        ssq += __shfl_xor_sync(0xffffffffu, ssq, off);
        ssk += __shfl_xor_sync(0xffffffffu, ssk, off);
    }
    float rq = rsqrtf(ssq*(1.f/HD) + EPS);
    float rk = rsqrtf(ssk*(1.f/HD) + EPS);
    q0 *= rq*qw[lane]; q1 *= rq*qw[lane+32];
    k0 *= rk*kw[lane]; k1 *= rk*kw[lane+32];
    size_t ko = ((((size_t)b*KVL + CCH + n)*2 + 0)*NH + h)*HD;
    kvout[ko + lane] = k0;            kvout[ko + lane + 32] = k1;
    size_t vo = ko + (size_t)NH*HD;
    kvout[vo + lane] = v0;            kvout[vo + lane + 32] = v1;
    // rope Q at pos CCH+n, scale 1/8, split hi/lo, layout [b,h,n,d]
    int ti = (CCH + n)*32 + lane;
    float s = rs_[ti], c = rc_[ti];
    float r0 = (q0*c - q1*s) * 0.125f;
    float r1 = (q1*c + q0*s) * 0.125f;
    size_t qo = (((size_t)b*NH + h)*NN + n)*HD;
    __nv_bfloat16 h0,l0,h1,l1;
    split2(r0,h0,l0); split2(r1,h1,l1);
    qsh[qo + lane] = h0;      qsl[qo + lane] = l0;
    qsh[qo + lane + 32] = h1; qsl[qo + lane + 32] = l1;
}

// ---------------- rope + split K, split V: kvout -> [b,h,p,d] bf16 hi/lo ----------------
__global__ void kvsplit_k(const float* __restrict__ kvout,
                          __nv_bfloat16* __restrict__ ksh, __nv_bfloat16* __restrict__ ksl,
                          __nv_bfloat16* __restrict__ vsh, __nv_bfloat16* __restrict__ vsl,
                          const float* __restrict__ rs_, const float* __restrict__ rc_) {
    int w = (blockIdx.x*blockDim.x + threadIdx.x) >> 5;
    int lane = threadIdx.x & 31;
    if (w >= BB*KVL*NH) return;
    int b = w / (KVL*NH), rem = w % (KVL*NH);
    int p = rem / NH, h = rem % NH;
    size_t ko = ((((size_t)b*KVL + p)*2 + 0)*NH + h)*HD;
    float k0 = kvout[ko + lane], k1 = kvout[ko + lane + 32];
    size_t vo = ko + (size_t)NH*HD;
    float v0 = kvout[vo + lane], v1 = kvout[vo + lane + 32];
    int ti = p*32 + lane;
    float s = rs_[ti], c = rc_[ti];
    float r0 = k0*c - k1*s;
    float r1 = k1*c + k0*s;
    size_t o = (((size_t)b*NH + h)*KVL + p)*HD;
    __nv_bfloat16 h0,l0,h1,l1;
    split2(r0,h0,l0); split2(r1,h1,l1);
    ksh[o + lane] = h0;      ksl[o + lane] = l0;
    ksh[o + lane + 32] = h1; ksl[o + lane + 32] = l1;
    split2(v0,h0,l0); split2(v1,h1,l1);
    vsh[o + lane] = h0;      vsl[o + lane] = l0;
    vsh[o + lane + 32] = h1; vsl[o + lane + 32] = l1;
}

// ================= flash attention with mma.sync (bf16 hi/lo) =================
// block = (64 q-rows, one (b,h)); 128 threads, 4 warps, warp w owns q rows [w*16, w*16+16)
// smem: Qh,Ql + double-buffered Kh,Kl,Vh,Vl tiles of [64][72] bf16 (144B rows)
#define FA_STRB 144
#define FA_TB   (64*FA_STRB)            // 9216 B per tile
#define FA_SQ   (2*FA_TB)               // Q region
#define FA_STG  (4*FA_TB)               // per stage (Kh,Kl,Vh,Vl)
#define FA_SMEM (FA_SQ + 2*FA_STG)      // 92160 B
#define FA_NT   (KVL/64)                // 40 kv tiles

__global__ void __launch_bounds__(128)
fa_mma_k(const __nv_bfloat16* __restrict__ Qh, const __nv_bfloat16* __restrict__ Ql,
         const __nv_bfloat16* __restrict__ Kh, const __nv_bfloat16* __restrict__ Kl,
         const __nv_bfloat16* __restrict__ Vh, const __nv_bfloat16* __restrict__ Vl,
         __nv_bfloat16* __restrict__ Oh, __nv_bfloat16* __restrict__ Ol){
    extern __shared__ char smc[];
    uint32_t sb = _s2u(smc);
    int qt = blockIdx.x, h = blockIdx.y, b = blockIdx.z;
    int tid = threadIdx.x, wid = tid>>5, lane = tid&31;

    size_t bh = (size_t)b*NH + h;
    const __nv_bfloat16* gqh = Qh + (bh*NN + qt*64)*HD;
    const __nv_bfloat16* gql = Ql + (bh*NN + qt*64)*HD;
    const __nv_bfloat16* gkh = Kh + bh*KVL*HD;
    const __nv_bfloat16* gkl = Kl + bh*KVL*HD;
    const __nv_bfloat16* gvh = Vh + bh*KVL*HD;
    const __nv_bfloat16* gvl = Vl + bh*KVL*HD;

    // --- load Q (group 0) ---
    #pragma unroll
    for (int i = 0; i < 8; i++){
        int idx = tid + i*128;              // 0..1023
        int t = idx >> 9, pos = idx & 511;
        int row = pos >> 3, seg = pos & 7;
        const __nv_bfloat16* g = (t ? gql : gqh) + (size_t)row*HD + seg*8;
        CP16(sb + t*FA_TB + row*FA_STRB + seg*16, g);
    }
    CPCOMMIT();
    // --- load KV tile 0 (group 1) ---
    {
        uint32_t st = sb + FA_SQ;
        #pragma unroll
        for (int i = 0; i < 16; i++){
            int idx = tid + i*128;          // 0..2047
            int t = idx >> 9, pos = idx & 511;
            int row = pos >> 3, seg = pos & 7;
            const __nv_bfloat16* g = (t==0? gkh : t==1? gkl : t==2? gvh : gvl)
                                   + (size_t)row*HD + seg*8;
            CP16(st + t*FA_TB + row*FA_STRB + seg*16, g);
        }
        CPCOMMIT();
    }

    // Q fragments (resident): wait for Q group only
    CPWAITG(1);
    __syncthreads();
    uint32_t qfh[4][4], qfl[4][4];
    {
        int arow = wid*16 + (lane & 15);
        int kc = (lane >> 4) * 8;
        #pragma unroll
        for (int kk = 0; kk < 4; kk++){
            uint32_t addr = sb + arow*FA_STRB + (kk*16 + kc)*2;
            ldsm_x4(addr, qfh[kk]);
            ldsm_x4(addr + FA_TB, qfl[kk]);
        }
    }

    float acc[8][4];
    #pragma unroll
    for (int j = 0; j < 8; j++){
        #pragma unroll
        for (int q = 0; q < 4; q++) acc[j][q] = 0.f;
    }
    float m0 = -1e30f, m1 = -1e30f, l0 = 0.f, l1 = 0.f;

    for (int it = 0; it < FA_NT; it++){
        // prefetch next tile into other stage
        if (it + 1 < FA_NT){
            uint32_t st = sb + FA_SQ + ((it+1)&1)*FA_STG;
            int p0 = (it+1)*64;
            #pragma unroll
            for (int i = 0; i < 16; i++){
                int idx = tid + i*128;
                int t = idx >> 9, pos = idx & 511;
                int row = pos >> 3, seg = pos & 7;
                const __nv_bfloat16* g = (t==0? gkh : t==1? gkl : t==2? gvh : gvl)
                                       + (size_t)(p0+row)*HD + seg*8;
                CP16(st + t*FA_TB + row*FA_STRB + seg*16, g);
            }
            CPCOMMIT();
        }
        if (it + 1 < FA_NT) { CPWAITG(1); } else { CPWAITG(0); }
        __syncthreads();

        uint32_t st = sb + FA_SQ + (it&1)*FA_STG;
        uint32_t smKh = st, smVh = st + 2*FA_TB;

        // ---- S = Q K^T ----
        float s[8][4];
        int l16 = lane & 15;
        int brow = lane & 7;
        int bkc = ((lane >> 3) & 1) * 8;
        #pragma unroll
        for (int j = 0; j < 8; j++){
            #pragma unroll
            for (int q = 0; q < 4; q++) s[j][q] = 0.f;
            #pragma unroll
            for (int kk = 0; kk < 4; kk++){
                uint32_t addr = smKh + (j*8 + brow)*FA_STRB + (kk*16 + bkc)*2;
                uint32_t kbh[2], kbl[2];
                ldsm_x2(addr, kbh);
                ldsm_x2(addr + FA_TB, kbl);        // Kl = Kh + 1 tile
                mma16816(s[j], qfh[kk], kbh);
                mma16816(s[j], qfh[kk], kbl);
                mma16816(s[j], qfl[kk], kbh);
            }
        }

        // ---- online softmax on fragments ----
        float mx0 = -1e30f, mx1 = -1e30f;
        #pragma unroll
        for (int j = 0; j < 8; j++){
            mx0 = fmaxf(mx0, fmaxf(s[j][0], s[j][1]));
            mx1 = fmaxf(mx1, fmaxf(s[j][2], s[j][3]));
        }
        #pragma unroll
        for (int off = 1; off < 4; off <<= 1){
            mx0 = fmaxf(mx0, __shfl_xor_sync(0xffffffffu, mx0, off));
            mx1 = fmaxf(mx1, __shfl_xor_sync(0xffffffffu, mx1, off));
        }
        float mn0 = fmaxf(m0, mx0), mn1 = fmaxf(m1, mx1);
        float c0 = __expf(m0 - mn0), c1 = __expf(m1 - mn1);
        m0 = mn0; m1 = mn1;
        l0 *= c0; l1 *= c1;
        #pragma unroll
        for (int j = 0; j < 8; j++){
            acc[j][0] *= c0; acc[j][1] *= c0;
            acc[j][2] *= c1; acc[j][3] *= c1;
        }
        // exp + pack P hi/lo into A-fragment words
        uint32_t phi[8][2], plo[8][2];
        #pragma unroll
        for (int j = 0; j < 8; j++){
            float p0 = __expf(s[j][0] - mn0);
            float p1 = __expf(s[j][1] - mn0);
            float p2 = __expf(s[j][2] - mn1);
            float p3 = __expf(s[j][3] - mn1);
            l0 += p0 + p1; l1 += p2 + p3;
            pack_hl(p0, p1, phi[j][0], plo[j][0]);
            pack_hl(p2, p3, phi[j][1], plo[j][1]);
        }

        // ---- O += P V ----
        #pragma unroll
        for (int kk = 0; kk < 4; kk++){
            uint32_t pah[4] = { phi[2*kk][0], phi[2*kk][1], phi[2*kk+1][0], phi[2*kk+1][1] };
            uint32_t pal[4] = { plo[2*kk][0], plo[2*kk][1], plo[2*kk+1][0], plo[2*kk+1][1] };
            #pragma unroll
            for (int j = 0; j < 8; j++){
                uint32_t addr = smVh + (kk*16 + l16)*FA_STRB + j*8*2;
                uint32_t vbh[2], vbl[2];
                ldsm_x2t(addr, vbh);
                ldsm_x2t(addr + FA_TB, vbl);       // Vl = Vh + 1 tile  (R11 bug: was +2*FA_TB)
                mma16816(acc[j], pah, vbh);
                mma16816(acc[j], pah, vbl);
                mma16816(acc[j], pal, vbh);
            }
        }
        __syncthreads();
    }

    // final l reduce across the 4-lane row group
    #pragma unroll
    for (int off = 1; off < 4; off <<= 1){
        l0 += __shfl_xor_sync(0xffffffffu, l0, off);
        l1 += __shfl_xor_sync(0xffffffffu, l1, off);
    }
    float rl0 = 1.f / l0, rl1 = 1.f / l1;

    int q0r = qt*64 + wid*16 + (lane >> 2);
    int cc = (lane & 3)*2;
    #pragma unroll
    for (int j = 0; j < 8; j++){
        int col = h*HD + j*8 + cc;
        float o0 = acc[j][0]*rl0, o1 = acc[j][1]*rl0;
        uint32_t hw, lw; pack_hl(o0, o1, hw, lw);
        size_t off0 = (size_t)(b*NN + q0r)*DM + col;
        *reinterpret_cast<uint32_t*>(&Oh[off0]) = hw;
        *reinterpret_cast<uint32_t*>(&Ol[off0]) = lw;
        float o2 = acc[j][2]*rl1, o3 = acc[j][3]*rl1;
        pack_hl(o2, o3, hw, lw);
        size_t off1 = (size_t)(b*NN + q0r + 8)*DM + col;
        *reinterpret_cast<uint32_t*>(&Oh[off1]) = hw;
        *reinterpret_cast<uint32_t*>(&Ol[off1]) = lw;
    }
}

// ---------------- GLU ----------------
__global__ void glu_k(const float* __restrict__ in, float* __restrict__ out) {
    int idx = blockIdx.x*blockDim.x + threadIdx.x;
    if (idx >= RR*DM) return;
    int r = idx / DM, c = idx % DM;
    float a = in[(size_t)r*(2*DM) + c];
    float g = in[(size_t)r*(2*DM) + DM + c];
    out[idx] = a / (1.f + expf(-g));
}

// ---------------- depthwise conv ----------------
__global__ void dwconv_k(const float* __restrict__ in, const float* __restrict__ w,
                         const float* __restrict__ bias, float* __restrict__ out) {
    int idx = blockIdx.x*blockDim.x + threadIdx.x;
    if (idx >= RR*DM) return;
    int c = idx % DM, bn = idx / DM;
    int n = bn % NN, b = bn / NN;
    const float* wr = w + c*KSZ;
    const float* base = in + (size_t)b*NN*DM + c;
    float acc = bias[c];
    #pragma unroll
    for (int t = 0; t < KSZ; t++) {
        int nn = n + t - (KSZ/2);
        if (nn >= 0 && nn < NN) acc += base[(size_t)nn*DM] * wr[t];
    }
    out[idx] = acc;
}

// ---------------- batchnorm stats ----------------
__global__ void bnstats_k(const float* __restrict__ x, float* __restrict__ mean,
                          float* __restrict__ var) {
    int c = blockIdx.x, tid = threadIdx.x;
    float s = 0.f, s2 = 0.f;
    for (int r = tid; r < RR; r += 256) {
        float v = x[(size_t)r*DM + c];
        s += v; s2 += v*v;
    }
    __shared__ float rs[256], rs2[256];
    rs[tid] = s; rs2[tid] = s2; __syncthreads();
    for (int k = 128; k > 0; k >>= 1) {
        if (tid < k) { rs[tid] += rs[tid+k]; rs2[tid] += rs2[tid+k]; }
        __syncthreads();
    }
    if (tid == 0) {
        float m = rs[0] * (1.f/RR);
        mean[c] = m;
        var[c] = rs2[0] * (1.f/RR) - m*m;
    }
}

// ---------------- batchnorm apply + swish -> bf16 hi/lo ----------------
__global__ void bnapply_split_k(const float* __restrict__ x, const float* __restrict__ mean,
                                const float* __restrict__ var, const float* __restrict__ g,
                                const float* __restrict__ b,
                                __nv_bfloat16* __restrict__ hi, __nv_bfloat16* __restrict__ lo) {
    int idx = blockIdx.x*blockDim.x + threadIdx.x;
    if (idx >= RR*DM) return;
    int c = idx % DM;
    float v = (x[idx] - mean[c]) * rsqrtf(var[c] + EPS) * g[c] + b[c];
    v = v / (1.f + expf(-v));
    __nv_bfloat16 h, l; split2(v, h, l);
    hi[idx] = h; lo[idx] = l;
}

// ---------------- launch ----------------
extern "C" void kernel_launch(void* const* d_in, const int* in_sizes, int n_in,
                              void* d_out, int out_size) {
    const float* x_in      = (const float*)d_in[0];
    const float* cached    = (const float*)d_in[4];
    const float* ff1_nw    = (const float*)d_in[5];
    const float* ff1_w1    = (const float*)d_in[6];
    const float* ff1_b1    = (const float*)d_in[7];
    const float* ff1_w2    = (const float*)d_in[8];
    const float* ff1_b2    = (const float*)d_in[9];
    const float* attn_nw   = (const float*)d_in[10];
    const float* qkv_w     = (const float*)d_in[11];
    const float* out_w     = (const float*)d_in[12];
    const float* q_nw      = (const float*)d_in[13];
    const float* k_nw      = (const float*)d_in[14];
    const float* conv_nw   = (const float*)d_in[15];
    const float* pw1_w     = (const float*)d_in[16];
    const float* pw1_b     = (const float*)d_in[17];
    const float* dw_w      = (const float*)d_in[18];
    const float* dw_b      = (const float*)d_in[19];
    const float* bn_g      = (const float*)d_in[20];
    const float* bn_b      = (const float*)d_in[21];
    const float* pw2_w     = (const float*)d_in[22];
    const float* pw2_b     = (const float*)d_in[23];
    const float* ff2_nw    = (const float*)d_in[24];
    const float* ff2_w1    = (const float*)d_in[25];
    const float* ff2_b1    = (const float*)d_in[26];
    const float* ff2_w2    = (const float*)d_in[27];
    const float* ff2_b2    = (const float*)d_in[28];
    const float* out_nw    = (const float*)d_in[29];

    float* outx  = (float*)d_out;
    float* kvout = outx + (size_t)RR*DM;

    float *x_, *ff_, *qkv_, *glu_, *dw_, *mean_, *var_, *rs_, *rc_;
    __nv_bfloat16 *wth_, *wtl_, *abh_, *abl_, *a1h_, *a1l_, *qsh_, *qsl_, *ksh_, *ksl_, *vsh_, *vsl_;
    cudaGetSymbolAddress((void**)&x_,    g_x);
    cudaGetSymbolAddress((void**)&ff_,   g_ff);
    cudaGetSymbolAddress((void**)&qkv_,  g_qkv);
    cudaGetSymbolAddress((void**)&glu_,  g_glu);
    cudaGetSymbolAddress((void**)&dw_,   g_dw);
    cudaGetSymbolAddress((void**)&mean_, g_mean);
    cudaGetSymbolAddress((void**)&var_,  g_var);
    cudaGetSymbolAddress((void**)&rs_,   g_rs);
    cudaGetSymbolAddress((void**)&rc_,   g_rc);
    cudaGetSymbolAddress((void**)&wth_,  g_wth);
    cudaGetSymbolAddress((void**)&wtl_,  g_wtl);
    cudaGetSymbolAddress((void**)&abh_,  g_abh);
    cudaGetSymbolAddress((void**)&abl_,  g_abl);
    cudaGetSymbolAddress((void**)&a1h_,  g_a1h);
    cudaGetSymbolAddress((void**)&a1l_,  g_a1l);
    cudaGetSymbolAddress((void**)&qsh_,  g_qsh);
    cudaGetSymbolAddress((void**)&qsl_,  g_qsl);
    cudaGetSymbolAddress((void**)&ksh_,  g_ksh);
    cudaGetSymbolAddress((void**)&ksl_,  g_ksl);
    cudaGetSymbolAddress((void**)&vsh_,  g_vsh);
    cudaGetSymbolAddress((void**)&vsl_,  g_vsl);

    static int attr_set = 0;
    if (!attr_set) {
        cudaFuncSetAttribute(fa_mma_k, cudaFuncAttributeMaxDynamicSharedMemorySize, FA_SMEM);
        cudaFuncSetAttribute(tgemm_k<0,0>, cudaFuncAttributeMaxDynamicSharedMemorySize, GSM);
        cudaFuncSetAttribute(tgemm_k<1,1>, cudaFuncAttributeMaxDynamicSharedMemorySize, GSM);
        cudaFuncSetAttribute(tgemm_k<2,0>, cudaFuncAttributeMaxDynamicSharedMemorySize, GSM);
        attr_set = 1;
    }

    // weight offsets (transposed [N,K] layouts)
    size_t o = 0;
    size_t off_qkv = o; o += (size_t)(3*NH*HD)*DM;
    size_t off_out = o; o += (size_t)DM*DM;
    size_t off_f1a = o; o += (size_t)FF*DM;
    size_t off_f1b = o; o += (size_t)DM*FF;
    size_t off_pw1 = o; o += (size_t)(2*DM)*DM;
    size_t off_pw2 = o; o += (size_t)DM*DM;
    size_t off_f2a = o; o += (size_t)FF*DM;
    size_t off_f2b = o; o += (size_t)DM*FF;

    dim3 tb(32,8);
    tsplit_k<<<dim3((3*NH*HD)/32, DM/32), tb>>>(qkv_w,  wth_+off_qkv, wtl_+off_qkv, DM, 3*NH*HD);
    tsplit_k<<<dim3(DM/32, DM/32),        tb>>>(out_w,  wth_+off_out, wtl_+off_out, DM, DM);
    tsplit_k<<<dim3(FF/32, DM/32),        tb>>>(ff1_w1, wth_+off_f1a, wtl_+off_f1a, DM, FF);
    tsplit_k<<<dim3(DM/32, FF/32),        tb>>>(ff1_w2, wth_+off_f1b, wtl_+off_f1b, FF, DM);
    tsplit_k<<<dim3((2*DM)/32, DM/32),    tb>>>(pw1_w,  wth_+off_pw1, wtl_+off_pw1, DM, 2*DM);
    tsplit_k<<<dim3(DM/32, DM/32),        tb>>>(pw2_w,  wth_+off_pw2, wtl_+off_pw2, DM, DM);
    tsplit_k<<<dim3(FF/32, DM/32),        tb>>>(ff2_w1, wth_+off_f2a, wtl_+off_f2a, DM, FF);
    tsplit_k<<<dim3(DM/32, FF/32),        tb>>>(ff2_w2, wth_+off_f2b, wtl_+off_f2b, FF, DM);
    rope_table_k<<<(KVL*32 + 255)/256, 256>>>(rs_, rc_);

    cudaMemcpyAsync(x_, x_in, sizeof(float)*(size_t)RR*DM, cudaMemcpyDeviceToDevice, 0);

    const int EW = (RR*DM + 255)/256;

    // ---- FF1
    rmsnorm_split_k<<<RR, 256>>>(x_, ff1_nw, a1h_, a1l_);
    tgemm_k<1,1><<<dim3(FF/128, RR/128), 256, GSM>>>(a1h_, a1l_, wth_+off_f1a, wtl_+off_f1a,
                                                     ff1_b1, nullptr, nullptr, abh_, abl_, FF, DM);
    tgemm_k<2,0><<<dim3(DM/128, RR/128), 256, GSM>>>(abh_, abl_, wth_+off_f1b, wtl_+off_f1b,
                                                     ff1_b2, x_, x_, nullptr, nullptr, DM, FF);

    // ---- Attention
    rmsnorm_split_k<<<RR, 256>>>(x_, attn_nw, a1h_, a1l_);
    tgemm_k<0,0><<<dim3((3*NH*HD)/128, RR/128), 256, GSM>>>(a1h_, a1l_, wth_+off_qkv, wtl_+off_qkv,
                                                            nullptr, nullptr, qkv_, nullptr, nullptr,
                                                            3*NH*HD, DM);
    copy_cache_k<<<(BB*CCH*2*NH*HD + 255)/256, 256>>>(cached, kvout);
    qkv_post_k<<<RR*NH/4, 128>>>(qkv_, q_nw, k_nw, kvout, qsh_, qsl_, rs_, rc_);
    kvsplit_k<<<BB*KVL*NH/4, 128>>>(kvout, ksh_, ksl_, vsh_, vsl_, rs_, rc_);
    fa_mma_k<<<dim3(NN/64, NH, BB), 128, FA_SMEM>>>(qsh_, qsl_, ksh_, ksl_, vsh_, vsl_, a1h_, a1l_);
    tgemm_k<0,0><<<dim3(DM/128, RR/128), 256, GSM>>>(a1h_, a1l_, wth_+off_out, wtl_+off_out,
                                                     nullptr, x_, x_, nullptr, nullptr, DM, DM);

    // ---- Conv module
    rmsnorm_split_k<<<RR, 256>>>(x_, conv_nw, a1h_, a1l_);
    tgemm_k<0,0><<<dim3((2*DM)/128, RR/128), 256, GSM>>>(a1h_, a1l_, wth_+off_pw1, wtl_+off_pw1,
                                                         pw1_b, nullptr, ff_, nullptr, nullptr,
                                                         2*DM, DM);
    glu_k<<<EW, 256>>>(ff_, glu_);
    dwconv_k<<<EW, 256>>>(glu_, dw_w, dw_b, dw_);
    bnstats_k<<<DM, 256>>>(dw_, mean_, var_);
    bnapply_split_k<<<EW, 256>>>(dw_, mean_, var_, bn_g, bn_b, a1h_, a1l_);
    tgemm_k<0,0><<<dim3(DM/128, RR/128), 256, GSM>>>(a1h_, a1l_, wth_+off_pw2, wtl_+off_pw2,
                                                     pw2_b, nullptr, x_, nullptr, nullptr, DM, DM);

    // ---- FF2
    rmsnorm_split_k<<<RR, 256>>>(x_, ff2_nw, a1h_, a1l_);
    tgemm_k<1,1><<<dim3(FF/128, RR/128), 256, GSM>>>(a1h_, a1l_, wth_+off_f2a, wtl_+off_f2a,
                                                     ff2_b1, nullptr, nullptr, abh_, abl_, FF, DM);
    tgemm_k<2,0><<<dim3(DM/128, RR/128), 256, GSM>>>(abh_, abl_, wth_+off_f2b, wtl_+off_f2b,
                                                     ff2_b2, x_, x_, nullptr, nullptr, DM, FF);

    // ---- final rmsnorm -> output x
    rmsnorm_k<<<RR, 256>>>(x_, out_nw, outx);
}

// round 13
// speedup vs baseline: 2.6844x; 1.0190x over previous
#include <cuda_runtime.h>
#include <cuda_bf16.h>
#include <math.h>
#include <stdint.h>

// ---------------- problem constants ----------------
#define BB    2
#define NN    2048
#define CCH   512
#define KVL   2560          // CCH + NN
#define DM    768
#define NH    12
#define HD    64
#define FF    3072
#define KSZ   31
#define RR    (BB*NN)       // 4096 token rows
#define EPS   1e-5f

// ---------------- scratch (static device memory; no allocs) ----------------
__device__ float g_x   [RR*DM];
__device__ float g_ff  [RR*FF];          // fp32 GEMM outputs (pw1)
__device__ float g_qkv [RR*3*NH*HD];
__device__ float g_glu [RR*DM];
__device__ float g_dw  [RR*DM];
__device__ float g_mean[DM];
__device__ float g_var [DM];
__device__ float g_rs  [KVL*32];         // rope sin table
__device__ float g_rc  [KVL*32];         // rope cos table
#define BN_BLKS 128
__device__ float g_bnp1[BN_BLKS*DM];     // bn partial sums
__device__ float g_bnp2[BN_BLKS*DM];     // bn partial sumsq

#define WT_TOTAL 13565952
__device__ __align__(256) __nv_bfloat16 g_wth[WT_TOTAL];   // transposed weights hi
__device__ __align__(256) __nv_bfloat16 g_wtl[WT_TOTAL];   // transposed weights lo
__device__ __align__(256) __nv_bfloat16 g_abh[RR*FF];      // FF-wide activation hi
__device__ __align__(256) __nv_bfloat16 g_abl[RR*FF];      // FF-wide activation lo
__device__ __align__(256) __nv_bfloat16 g_a1h[RR*DM];      // DM-wide activation hi
__device__ __align__(256) __nv_bfloat16 g_a1l[RR*DM];      // DM-wide activation lo
__device__ __align__(256) __nv_bfloat16 g_qsh[RR*DM];      // Q split hi  [b,h,n,d] (scaled)
__device__ __align__(256) __nv_bfloat16 g_qsl[RR*DM];
#define KVE (BB*NH*KVL*HD)
__device__ __align__(256) __nv_bfloat16 g_ksh[KVE];        // roped K hi [b,h,p,d]
__device__ __align__(256) __nv_bfloat16 g_ksl[KVE];
__device__ __align__(256) __nv_bfloat16 g_vsh[KVE];        // V hi [b,h,p,d]
__device__ __align__(256) __nv_bfloat16 g_vsl[KVE];

// ================= PTX helpers (base sm_103-safe) ====
__device__ __forceinline__ uint32_t _s2u(const void* p){
    uint32_t a; asm("{ .reg .u64 t; cvta.to.shared.u64 t, %1; cvt.u32.u64 %0, t; }":"=r"(a):"l"(p)); return a;
}
#define CP16(d,s)   asm volatile("cp.async.cg.shared.global [%0], [%1], 16;"::"r"(d),"l"(s):"memory")
#define CPCOMMIT()  asm volatile("cp.async.commit_group;":::"memory")
#define CPWAITG(n)  asm volatile("cp.async.wait_group %0;"::"n"(n):"memory")

__device__ __forceinline__ void ldsm_x4(uint32_t a, uint32_t r[4]){
    asm volatile("ldmatrix.sync.aligned.m8n8.x4.shared.b16 {%0,%1,%2,%3}, [%4];"
        : "=r"(r[0]),"=r"(r[1]),"=r"(r[2]),"=r"(r[3]) : "r"(a));
}
__device__ __forceinline__ void ldsm_x2(uint32_t a, uint32_t r[2]){
    asm volatile("ldmatrix.sync.aligned.m8n8.x2.shared.b16 {%0,%1}, [%2];"
        : "=r"(r[0]),"=r"(r[1]) : "r"(a));
}
__device__ __forceinline__ void ldsm_x2t(uint32_t a, uint32_t r[2]){
    asm volatile("ldmatrix.sync.aligned.m8n8.x2.trans.shared.b16 {%0,%1}, [%2];"
        : "=r"(r[0]),"=r"(r[1]) : "r"(a));
}
__device__ __forceinline__ void mma16816(float d[4], const uint32_t a[4], const uint32_t b[2]){
    asm volatile("mma.sync.aligned.m16n8k16.row.col.f32.bf16.bf16.f32 "
        "{%0,%1,%2,%3}, {%4,%5,%6,%7}, {%8,%9}, {%0,%1,%2,%3};"
        : "+f"(d[0]),"+f"(d[1]),"+f"(d[2]),"+f"(d[3])
        : "r"(a[0]),"r"(a[1]),"r"(a[2]),"r"(a[3]), "r"(b[0]),"r"(b[1]));
}

__device__ __forceinline__ void split2(float v, __nv_bfloat16& h, __nv_bfloat16& l){
    h = __float2bfloat16(v);
    l = __float2bfloat16(v - __bfloat162float(h));
}
// pack two floats into bf16x2 hi and lo (residual) words; low 16 bits = first arg
__device__ __forceinline__ void pack_hl(float p0, float p1, uint32_t& hi, uint32_t& lo){
    __nv_bfloat162 th, tl;
    th.x = __float2bfloat16(p0); th.y = __float2bfloat16(p1);
    tl.x = __float2bfloat16(p0 - __bfloat162float(th.x));
    tl.y = __float2bfloat16(p1 - __bfloat162float(th.y));
    hi = *reinterpret_cast<uint32_t*>(&th);
    lo = *reinterpret_cast<uint32_t*>(&tl);
}

// ================= bf16x3 mma.sync GEMM =================
#define KC      32
#define ROWSTR  80
#define TILEB   (128*ROWSTR)
#define STAGEB  (4*TILEB)
#define GSM     (2*STAGEB)

__device__ __forceinline__ void g_load_chunk(uint32_t sbase, int stage, int tid,
        const __nv_bfloat16* a0, const __nv_bfloat16* a1,
        const __nv_bfloat16* b0, const __nv_bfloat16* b1, int K, int koff){
    uint32_t st = sbase + stage*STAGEB;
    #pragma unroll
    for (int t = 0; t < 4; t++){
        const __nv_bfloat16* src = (t==0? a0 : t==1? a1 : t==2? b0 : b1);
        uint32_t tb = st + t*TILEB;
        #pragma unroll
        for (int s = 0; s < 2; s++){
            int idx = tid + s*256;
            int row = idx >> 2, seg = idx & 3;
            const __nv_bfloat16* g = src + (size_t)row*K + koff + seg*8;
            CP16(tb + row*ROWSTR + seg*16, g);
        }
    }
}

template<int ACT, int OUTB>
__global__ void __launch_bounds__(256)
tgemm_k(const __nv_bfloat16* __restrict__ Ah, const __nv_bfloat16* __restrict__ Al,
        const __nv_bfloat16* __restrict__ Bh, const __nv_bfloat16* __restrict__ Bl,
        const float* __restrict__ bias, const float* __restrict__ resid,
        float* __restrict__ C, __nv_bfloat16* __restrict__ Ch, __nv_bfloat16* __restrict__ Cl,
        int Nn, int K){
    extern __shared__ char smc[];
    uint32_t sb = _s2u(smc);
    int tid = threadIdx.x, wid = tid>>5, lane = tid&31;
    int wm = wid>>2, wn = wid&3;
    int bm = blockIdx.y*128, bn = blockIdx.x*128;

    const __nv_bfloat16* a0 = Ah + (size_t)bm*K;
    const __nv_bfloat16* a1 = Al + (size_t)bm*K;
    const __nv_bfloat16* b0 = Bh + (size_t)bn*K;
    const __nv_bfloat16* b1 = Bl + (size_t)bn*K;
    int nk = K/KC;

    float acc[4][4][4];
    #pragma unroll
    for (int i = 0; i < 4; i++){
        #pragma unroll
        for (int j = 0; j < 4; j++){
            #pragma unroll
            for (int q = 0; q < 4; q++) acc[i][j][q] = 0.f;
        }
    }

    g_load_chunk(sb, 0, tid, a0,a1,b0,b1, K, 0);
    CPCOMMIT();
    g_load_chunk(sb, 1, tid, a0,a1,b0,b1, K, KC);
    CPCOMMIT();

    int arow = (lane & 15);
    int akhi = (lane >> 4) * 8;
    int brow = (lane & 7);
    int bkhi = ((lane >> 3) & 1) * 8;

    for (int c = 0; c < nk; c++){
        if (c+1 < nk) { CPWAITG(1); } else { CPWAITG(0); }
        __syncthreads();
        uint32_t st = sb + (c&1)*STAGEB;
        uint32_t Abase = st + (wm*64 + arow)*ROWSTR;
        uint32_t Bbase = st + 2*TILEB + (wn*32 + brow)*ROWSTR;
        #pragma unroll
        for (int kk2 = 0; kk2 < 2; kk2++){
            int kca = (kk2*16 + akhi)*2;
            int kcb = (kk2*16 + bkhi)*2;
            uint32_t ah[4][4], al[4][4], bh[4][2], bl[4][2];
            #pragma unroll
            for (int mi = 0; mi < 4; mi++){
                uint32_t addr = Abase + mi*16*ROWSTR + kca;
                ldsm_x4(addr, ah[mi]);
                ldsm_x4(addr + TILEB, al[mi]);
            }
            #pragma unroll
            for (int ni = 0; ni < 4; ni++){
                uint32_t addr = Bbase + ni*8*ROWSTR + kcb;
                ldsm_x2(addr, bh[ni]);
                ldsm_x2(addr + TILEB, bl[ni]);
            }
            #pragma unroll
            for (int mi = 0; mi < 4; mi++){
                #pragma unroll
                for (int ni = 0; ni < 4; ni++){
                    mma16816(acc[mi][ni], ah[mi], bh[ni]);
                    mma16816(acc[mi][ni], ah[mi], bl[ni]);
                    mma16816(acc[mi][ni], al[mi], bh[ni]);
                }
            }
        }
        __syncthreads();
        if (c+2 < nk){
            g_load_chunk(sb, c&1, tid, a0,a1,b0,b1, K, (c+2)*KC);
            CPCOMMIT();
        }
    }

    int r_in = lane >> 2, c_in = (lane & 3)*2;
    #pragma unroll
    for (int mi = 0; mi < 4; mi++){
        #pragma unroll
        for (int ni = 0; ni < 4; ni++){
            int gr = bm + wm*64 + mi*16 + r_in;
            int gc = bn + wn*32 + ni*8 + c_in;
            float b0v = bias ? bias[gc]   : 0.f;
            float b1v = bias ? bias[gc+1] : 0.f;
            #pragma unroll
            for (int half = 0; half < 2; half++){
                int rr = gr + half*8;
                float v0 = acc[mi][ni][half*2+0] + b0v;
                float v1 = acc[mi][ni][half*2+1] + b1v;
                if (ACT == 1){
                    float u = v0; v0 = 0.5f*u*(1.f+tanhf(0.7978845608028654f*(u+0.044715f*u*u*u)));
                    u = v1;       v1 = 0.5f*u*(1.f+tanhf(0.7978845608028654f*(u+0.044715f*u*u*u)));
                }
                if (ACT == 2){ v0 *= 0.5f; v1 *= 0.5f; }
                if (resid){
                    v0 += resid[(size_t)rr*Nn + gc];
                    v1 += resid[(size_t)rr*Nn + gc + 1];
                }
                if (OUTB){
                    uint32_t hw, lw;
                    pack_hl(v0, v1, hw, lw);
                    *reinterpret_cast<uint32_t*>(&Ch[(size_t)rr*Nn + gc]) = hw;
                    *reinterpret_cast<uint32_t*>(&Cl[(size_t)rr*Nn + gc]) = lw;
                } else {
                    float2 o; o.x = v0; o.y = v1;
                    *(float2*)&C[(size_t)rr*Nn + gc] = o;
                }
            }
        }
    }
}

// ---------------- fused transpose+split of ALL weights: one launch ----------------
// 8 segments, each W[K,N] fp32 -> hi/lo [N,K] bf16 at dstOff. 32x32 tiles.
__global__ void __launch_bounds__(256)
wsplit_all_k(const float* __restrict__ w0, const float* __restrict__ w1,
             const float* __restrict__ w2, const float* __restrict__ w3,
             const float* __restrict__ w4, const float* __restrict__ w5,
             const float* __restrict__ w6, const float* __restrict__ w7,
             __nv_bfloat16* __restrict__ hi, __nv_bfloat16* __restrict__ lo){
    const int   segStart[9] = {0,1728,2304,4608,6912,8064,8640,10944,13248};
    const int   segK[8]     = {768,768,768,3072,768,768,768,3072};
    const int   segN[8]     = {2304,768,3072,768,1536,768,3072,768};
    const size_t segDst[8]  = {0ul,1769472ul,2359296ul,4718592ul,7077888ul,8257536ul,8847360ul,11206656ul};

    int bid = blockIdx.x;
    int s = 0;
    #pragma unroll
    for (int i = 0; i < 8; i++) if (bid >= segStart[i+1]) s = i+1;
    const float* W;
    switch (s){
        case 0: W = w0; break; case 1: W = w1; break; case 2: W = w2; break;
        case 3: W = w3; break; case 4: W = w4; break; case 5: W = w5; break;
        case 6: W = w6; break; default: W = w7; break;
    }
    int K = segK[s], N = segN[s];
    int local = bid - segStart[s];
    int tilesN = N >> 5;
    int bn = (local % tilesN) << 5;
    int bk = (local / tilesN) << 5;

    __shared__ float tile[32][33];
    int tx = threadIdx.x & 31, ty = threadIdx.x >> 5;   // 32 x 8
    for (int i = ty; i < 32; i += 8) tile[i][tx] = W[(size_t)(bk+i)*N + bn+tx];
    __syncthreads();
    __nv_bfloat16* hseg = hi + segDst[s];
    __nv_bfloat16* lseg = lo + segDst[s];
    for (int i = ty; i < 32; i += 8){
        float v = tile[tx][i];                 // = W[bk+tx][bn+i]
        __nv_bfloat16 h, l; split2(v, h, l);
        size_t o = (size_t)(bn+i)*K + bk+tx;
        hseg[o]=h; lseg[o]=l;
    }
}

// ---------------- rope table ----------------
__global__ void rope_table_k(float* __restrict__ sins, float* __restrict__ coss){
    int idx = blockIdx.x*blockDim.x + threadIdx.x;
    if (idx >= KVL*32) return;
    int p = idx>>5, lane = idx&31;
    double inv = exp(-(double)lane * 0.28782313662425575);
    double sd, cd; sincos((double)p*inv, &sd, &cd);
    sins[idx]=(float)sd; coss[idx]=(float)cd;
}

// ---------------- rmsnorm -> bf16 hi/lo split ----------------
__global__ void rmsnorm_split_k(const float* __restrict__ x, const float* __restrict__ w,
                                __nv_bfloat16* __restrict__ hi, __nv_bfloat16* __restrict__ lo) {
    int r = blockIdx.x, tid = threadIdx.x;
    const float* xr = x + (size_t)r*DM;
    float ss = 0.f;
    for (int i = tid; i < DM; i += 256) { float v = xr[i]; ss += v*v; }
    __shared__ float red[256];
    red[tid] = ss; __syncthreads();
    for (int s = 128; s > 0; s >>= 1) { if (tid < s) red[tid] += red[tid+s]; __syncthreads(); }
    float rs = rsqrtf(red[0] * (1.f/DM) + EPS);
    for (int i = tid; i < DM; i += 256){
        float v = xr[i]*rs*w[i];
        __nv_bfloat16 h, l; split2(v, h, l);
        hi[(size_t)r*DM + i] = h; lo[(size_t)r*DM + i] = l;
    }
}

// ---------------- plain rmsnorm (final) ----------------
__global__ void rmsnorm_k(const float* __restrict__ x, const float* __restrict__ w,
                          float* __restrict__ y) {
    int r = blockIdx.x, tid = threadIdx.x;
    const float* xr = x + (size_t)r*DM;
    float ss = 0.f;
    for (int i = tid; i < DM; i += 256) { float v = xr[i]; ss += v*v; }
    __shared__ float red[256];
    red[tid] = ss; __syncthreads();
    for (int s = 128; s > 0; s >>= 1) { if (tid < s) red[tid] += red[tid+s]; __syncthreads(); }
    float rs = rsqrtf(red[0] * (1.f/DM) + EPS);
    float* yr = y + (size_t)r*DM;
    for (int i = tid; i < DM; i += 256) yr[i] = xr[i]*rs*w[i];
}

// ---------------- kv cache copy ----------------
__global__ void copy_cache_k(const float* __restrict__ cached, float* __restrict__ kvout) {
    int idx = blockIdx.x*blockDim.x + threadIdx.x;
    const int per = CCH*2*NH*HD;
    const int tot = BB*per;
    if (idx >= tot) return;
    int b = idx / per, r = idx % per;
    kvout[(size_t)b*KVL*2*NH*HD + r] = cached[idx];
}

// ---------------- qkv post: head rmsnorm, K/V -> cache, rope+scale+split Q ----------------
__global__ void qkv_post_k(const float* __restrict__ qkv, const float* __restrict__ qw,
                           const float* __restrict__ kw, float* __restrict__ kvout,
                           __nv_bfloat16* __restrict__ qsh, __nv_bfloat16* __restrict__ qsl,
                           const float* __restrict__ rs_, const float* __restrict__ rc_) {
    int w = (blockIdx.x*blockDim.x + threadIdx.x) >> 5;
    int lane = threadIdx.x & 31;
    if (w >= RR*NH) return;
    int b = w / (NN*NH), rem = w % (NN*NH);
    int n = rem / NH, h = rem % NH;
    const float* base = qkv + (size_t)(b*NN + n)*(3*NH*HD) + h*HD*3;
    float q0 = base[lane*3+0],      q1 = base[(lane+32)*3+0];
    float k0 = base[lane*3+1],      k1 = base[(lane+32)*3+1];
    float v0 = base[lane*3+2],      v1 = base[(lane+32)*3+2];
    float ssq = q0*q0 + q1*q1, ssk = k0*k0 + k1*k1;
    #pragma unroll
    for (int off = 16; off; off >>= 1) {
        ssq += __shfl_xor_sync(0xffffffffu, ssq, off);
        ssk += __shfl_xor_sync(0xffffffffu, ssk, off);
    }
    float rq = rsqrtf(ssq*(1.f/HD) + EPS);
    float rk = rsqrtf(ssk*(1.f/HD) + EPS);
    q0 *= rq*qw[lane]; q1 *= rq*qw[lane+32];
    k0 *= rk*kw[lane]; k1 *= rk*kw[lane+32];
    size_t ko = ((((size_t)b*KVL + CCH + n)*2 + 0)*NH + h)*HD;
    kvout[ko + lane] = k0;            kvout[ko + lane + 32] = k1;
    size_t vo = ko + (size_t)NH*HD;
    kvout[vo + lane] = v0;            kvout[vo + lane + 32] = v1;
    // rope Q at pos CCH+n, scale 1/8, split hi/lo, layout [b,h,n,d]
    int ti = (CCH + n)*32 + lane;
    float s = rs_[ti], c = rc_[ti];
    float r0 = (q0*c - q1*s) * 0.125f;
    float r1 = (q1*c + q0*s) * 0.125f;
    size_t qo = (((size_t)b*NH + h)*NN + n)*HD;
    __nv_bfloat16 h0,l0,h1,l1;
    split2(r0,h0,l0); split2(r1,h1,l1);
    qsh[qo + lane] = h0;      qsl[qo + lane] = l0;
    qsh[qo + lane + 32] = h1; qsl[qo + lane + 32] = l1;
}

// ---------------- rope + split K, split V: kvout -> [b,h,p,d] bf16 hi/lo ----------------
__global__ void kvsplit_k(const float* __restrict__ kvout,
                          __nv_bfloat16* __restrict__ ksh, __nv_bfloat16* __restrict__ ksl,
                          __nv_bfloat16* __restrict__ vsh, __nv_bfloat16* __restrict__ vsl,
                          const float* __restrict__ rs_, const float* __restrict__ rc_) {
    int w = (blockIdx.x*blockDim.x + threadIdx.x) >> 5;
    int lane = threadIdx.x & 31;
    if (w >= BB*KVL*NH) return;
    int b = w / (KVL*NH), rem = w % (KVL*NH);
    int p = rem / NH, h = rem % NH;
    size_t ko = ((((size_t)b*KVL + p)*2 + 0)*NH + h)*HD;
    float k0 = kvout[ko + lane], k1 = kvout[ko + lane + 32];
    size_t vo = ko + (size_t)NH*HD;
    float v0 = kvout[vo + lane], v1 = kvout[vo + lane + 32];
    int ti = p*32 + lane;
    float s = rs_[ti], c = rc_[ti];
    float r0 = k0*c - k1*s;
    float r1 = k1*c + k0*s;
    size_t o = (((size_t)b*NH + h)*KVL + p)*HD;
    __nv_bfloat16 h0,l0,h1,l1;
    split2(r0,h0,l0); split2(r1,h1,l1);
    ksh[o + lane] = h0;      ksl[o + lane] = l0;
    ksh[o + lane + 32] = h1; ksl[o + lane + 32] = l1;
    split2(v0,h0,l0); split2(v1,h1,l1);
    vsh[o + lane] = h0;      vsl[o + lane] = l0;
    vsh[o + lane + 32] = h1; vsl[o + lane + 32] = l1;
}

// ================= flash attention with mma.sync (bf16 hi/lo) =================
#define FA_STRB 144
#define FA_TB   (64*FA_STRB)            // 9216 B per tile
#define FA_SQ   (2*FA_TB)               // Q region
#define FA_STG  (4*FA_TB)               // per stage (Kh,Kl,Vh,Vl)
#define FA_SMEM (FA_SQ + 2*FA_STG)      // 92160 B
#define FA_NT   (KVL/64)                // 40 kv tiles

__global__ void __launch_bounds__(128)
fa_mma_k(const __nv_bfloat16* __restrict__ Qh, const __nv_bfloat16* __restrict__ Ql,
         const __nv_bfloat16* __restrict__ Kh, const __nv_bfloat16* __restrict__ Kl,
         const __nv_bfloat16* __restrict__ Vh, const __nv_bfloat16* __restrict__ Vl,
         __nv_bfloat16* __restrict__ Oh, __nv_bfloat16* __restrict__ Ol){
    extern __shared__ char smc[];
    uint32_t sb = _s2u(smc);
    int qt = blockIdx.x, h = blockIdx.y, b = blockIdx.z;
    int tid = threadIdx.x, wid = tid>>5, lane = tid&31;

    size_t bh = (size_t)b*NH + h;
    const __nv_bfloat16* gqh = Qh + (bh*NN + qt*64)*HD;
    const __nv_bfloat16* gql = Ql + (bh*NN + qt*64)*HD;
    const __nv_bfloat16* gkh = Kh + bh*KVL*HD;
    const __nv_bfloat16* gkl = Kl + bh*KVL*HD;
    const __nv_bfloat16* gvh = Vh + bh*KVL*HD;
    const __nv_bfloat16* gvl = Vl + bh*KVL*HD;

    // --- load Q (group 0) ---
    #pragma unroll
    for (int i = 0; i < 8; i++){
        int idx = tid + i*128;              // 0..1023
        int t = idx >> 9, pos = idx & 511;
        int row = pos >> 3, seg = pos & 7;
        const __nv_bfloat16* g = (t ? gql : gqh) + (size_t)row*HD + seg*8;
        CP16(sb + t*FA_TB + row*FA_STRB + seg*16, g);
    }
    CPCOMMIT();
    // --- load KV tile 0 (group 1) ---
    {
        uint32_t st = sb + FA_SQ;
        #pragma unroll
        for (int i = 0; i < 16; i++){
            int idx = tid + i*128;          // 0..2047
            int t = idx >> 9, pos = idx & 511;
            int row = pos >> 3, seg = pos & 7;
            const __nv_bfloat16* g = (t==0? gkh : t==1? gkl : t==2? gvh : gvl)
                                   + (size_t)row*HD + seg*8;
            CP16(st + t*FA_TB + row*FA_STRB + seg*16, g);
        }
        CPCOMMIT();
    }

    // Q fragments (resident): wait for Q group only
    CPWAITG(1);
    __syncthreads();
    uint32_t qfh[4][4], qfl[4][4];
    {
        int arow = wid*16 + (lane & 15);
        int kc = (lane >> 4) * 8;
        #pragma unroll
        for (int kk = 0; kk < 4; kk++){
            uint32_t addr = sb + arow*FA_STRB + (kk*16 + kc)*2;
            ldsm_x4(addr, qfh[kk]);
            ldsm_x4(addr + FA_TB, qfl[kk]);
        }
    }

    float acc[8][4];
    #pragma unroll
    for (int j = 0; j < 8; j++){
        #pragma unroll
        for (int q = 0; q < 4; q++) acc[j][q] = 0.f;
    }
    float m0 = -1e30f, m1 = -1e30f, l0 = 0.f, l1 = 0.f;

    for (int it = 0; it < FA_NT; it++){
        // prefetch next tile into other stage
        if (it + 1 < FA_NT){
            uint32_t st = sb + FA_SQ + ((it+1)&1)*FA_STG;
            int p0 = (it+1)*64;
            #pragma unroll
            for (int i = 0; i < 16; i++){
                int idx = tid + i*128;
                int t = idx >> 9, pos = idx & 511;
                int row = pos >> 3, seg = pos & 7;
                const __nv_bfloat16* g = (t==0? gkh : t==1? gkl : t==2? gvh : gvl)
                                       + (size_t)(p0+row)*HD + seg*8;
                CP16(st + t*FA_TB + row*FA_STRB + seg*16, g);
            }
            CPCOMMIT();
        }
        if (it + 1 < FA_NT) { CPWAITG(1); } else { CPWAITG(0); }
        __syncthreads();

        uint32_t st = sb + FA_SQ + (it&1)*FA_STG;
        uint32_t smKh = st, smVh = st + 2*FA_TB;

        // ---- S = Q K^T ----
        float s[8][4];
        int l16 = lane & 15;
        int brow = lane & 7;
        int bkc = ((lane >> 3) & 1) * 8;
        #pragma unroll
        for (int j = 0; j < 8; j++){
            #pragma unroll
            for (int q = 0; q < 4; q++) s[j][q] = 0.f;
            #pragma unroll
            for (int kk = 0; kk < 4; kk++){
                uint32_t addr = smKh + (j*8 + brow)*FA_STRB + (kk*16 + bkc)*2;
                uint32_t kbh[2], kbl[2];
                ldsm_x2(addr, kbh);
                ldsm_x2(addr + FA_TB, kbl);        // Kl = Kh + 1 tile
                mma16816(s[j], qfh[kk], kbh);
                mma16816(s[j], qfh[kk], kbl);
                mma16816(s[j], qfl[kk], kbh);
            }
        }

        // ---- online softmax on fragments ----
        float mx0 = -1e30f, mx1 = -1e30f;
        #pragma unroll
        for (int j = 0; j < 8; j++){
            mx0 = fmaxf(mx0, fmaxf(s[j][0], s[j][1]));
            mx1 = fmaxf(mx1, fmaxf(s[j][2], s[j][3]));
        }
        #pragma unroll
        for (int off = 1; off < 4; off <<= 1){
            mx0 = fmaxf(mx0, __shfl_xor_sync(0xffffffffu, mx0, off));
            mx1 = fmaxf(mx1, __shfl_xor_sync(0xffffffffu, mx1, off));
        }
        float mn0 = fmaxf(m0, mx0), mn1 = fmaxf(m1, mx1);
        float c0 = __expf(m0 - mn0), c1 = __expf(m1 - mn1);
        m0 = mn0; m1 = mn1;
        l0 *= c0; l1 *= c1;
        #pragma unroll
        for (int j = 0; j < 8; j++){
            acc[j][0] *= c0; acc[j][1] *= c0;
            acc[j][2] *= c1; acc[j][3] *= c1;
        }
        // exp + pack P hi/lo into A-fragment words
        uint32_t phi[8][2], plo[8][2];
        #pragma unroll
        for (int j = 0; j < 8; j++){
            float p0 = __expf(s[j][0] - mn0);
            float p1 = __expf(s[j][1] - mn0);
            float p2 = __expf(s[j][2] - mn1);
            float p3 = __expf(s[j][3] - mn1);
            l0 += p0 + p1; l1 += p2 + p3;
            pack_hl(p0, p1, phi[j][0], plo[j][0]);
            pack_hl(p2, p3, phi[j][1], plo[j][1]);
        }

        // ---- O += P V ----
        #pragma unroll
        for (int kk = 0; kk < 4; kk++){
            uint32_t pah[4] = { phi[2*kk][0], phi[2*kk][1], phi[2*kk+1][0], phi[2*kk+1][1] };
            uint32_t pal[4] = { plo[2*kk][0], plo[2*kk][1], plo[2*kk+1][0], plo[2*kk+1][1] };
            #pragma unroll
            for (int j = 0; j < 8; j++){
                uint32_t addr = smVh + (kk*16 + l16)*FA_STRB + j*8*2;
                uint32_t vbh[2], vbl[2];
                ldsm_x2t(addr, vbh);
                ldsm_x2t(addr + FA_TB, vbl);       // Vl = Vh + 1 tile
                mma16816(acc[j], pah, vbh);
                mma16816(acc[j], pah, vbl);
                mma16816(acc[j], pal, vbh);
            }
        }
        __syncthreads();
    }

    // final l reduce across the 4-lane row group
    #pragma unroll
    for (int off = 1; off < 4; off <<= 1){
        l0 += __shfl_xor_sync(0xffffffffu, l0, off);
        l1 += __shfl_xor_sync(0xffffffffu, l1, off);
    }
    float rl0 = 1.f / l0, rl1 = 1.f / l1;

    int q0r = qt*64 + wid*16 + (lane >> 2);
    int cc = (lane & 3)*2;
    #pragma unroll
    for (int j = 0; j < 8; j++){
        int col = h*HD + j*8 + cc;
        float o0 = acc[j][0]*rl0, o1 = acc[j][1]*rl0;
        uint32_t hw, lw; pack_hl(o0, o1, hw, lw);
        size_t off0 = (size_t)(b*NN + q0r)*DM + col;
        *reinterpret_cast<uint32_t*>(&Oh[off0]) = hw;
        *reinterpret_cast<uint32_t*>(&Ol[off0]) = lw;
        float o2 = acc[j][2]*rl1, o3 = acc[j][3]*rl1;
        pack_hl(o2, o3, hw, lw);
        size_t off1 = (size_t)(b*NN + q0r + 8)*DM + col;
        *reinterpret_cast<uint32_t*>(&Oh[off1]) = hw;
        *reinterpret_cast<uint32_t*>(&Ol[off1]) = lw;
    }
}

// ---------------- GLU ----------------
__global__ void glu_k(const float* __restrict__ in, float* __restrict__ out) {
    int idx = blockIdx.x*blockDim.x + threadIdx.x;
    if (idx >= RR*DM) return;
    int r = idx / DM, c = idx % DM;
    float a = in[(size_t)r*(2*DM) + c];
    float g = in[(size_t)r*(2*DM) + DM + c];
    out[idx] = a / (1.f + expf(-g));
}

// ---------------- depthwise conv: 8 outputs/thread, register sliding window ----------------
// block: 256 threads, handles 8 consecutive n for all 768 channels (3 per thread).
__global__ void __launch_bounds__(256)
dwconv8_k(const float* __restrict__ in, const float* __restrict__ w,
          const float* __restrict__ bias, float* __restrict__ out) {
    int n8 = blockIdx.x;                 // 0..NN/8-1
    int b  = blockIdx.y;
    int n0 = n8*8;
    const float* bin = in + (size_t)b*NN*DM;
    float* bout = out + (size_t)b*NN*DM;
    #pragma unroll
    for (int cc = 0; cc < 3; cc++){
        int c = threadIdx.x + cc*256;
        const float* wr = w + c*KSZ;
        float win[38];
        #pragma unroll
        for (int j = 0; j < 38; j++){
            int nn = n0 + j - (KSZ/2);
            win[j] = (nn >= 0 && nn < NN) ? bin[(size_t)nn*DM + c] : 0.f;
        }
        float bv = bias[c];
        float acc[8];
        #pragma unroll
        for (int i = 0; i < 8; i++) acc[i] = bv;
        #pragma unroll
        for (int t = 0; t < KSZ; t++){
            float wv = wr[t];
            #pragma unroll
            for (int i = 0; i < 8; i++) acc[i] += win[i+t]*wv;
        }
        #pragma unroll
        for (int i = 0; i < 8; i++) bout[(size_t)(n0+i)*DM + c] = acc[i];
    }
}

// ---------------- batchnorm stats pass1: coalesced partial sums ----------------
// 128 blocks x 256 threads; block handles 32 rows, all 768 channels (3 per thread).
__global__ void __launch_bounds__(256)
bnstats1_k(const float* __restrict__ x, float* __restrict__ p1, float* __restrict__ p2) {
    int blk = blockIdx.x;
    int r0 = blk * (RR/BN_BLKS);
    #pragma unroll
    for (int cc = 0; cc < 3; cc++){
        int c = threadIdx.x + cc*256;
        float s = 0.f, s2 = 0.f;
        #pragma unroll 4
        for (int r = 0; r < RR/BN_BLKS; r++){
            float v = x[(size_t)(r0+r)*DM + c];
            s += v; s2 += v*v;
        }
        p1[(size_t)blk*DM + c] = s;
        p2[(size_t)blk*DM + c] = s2;
    }
}

// ---------------- batchnorm stats pass2 ----------------
__global__ void bnstats2_k(const float* __restrict__ p1, const float* __restrict__ p2,
                           float* __restrict__ mean, float* __restrict__ var) {
    int c = blockIdx.x*blockDim.x + threadIdx.x;
    if (c >= DM) return;
    float s = 0.f, s2 = 0.f;
    for (int b = 0; b < BN_BLKS; b++){
        s  += p1[(size_t)b*DM + c];
        s2 += p2[(size_t)b*DM + c];
    }
    float m = s * (1.f/RR);
    mean[c] = m;
    var[c] = s2 * (1.f/RR) - m*m;
}

// ---------------- batchnorm apply + swish -> bf16 hi/lo ----------------
__global__ void bnapply_split_k(const float* __restrict__ x, const float* __restrict__ mean,
                                const float* __restrict__ var, const float* __restrict__ g,
                                const float* __restrict__ b,
                                __nv_bfloat16* __restrict__ hi, __nv_bfloat16* __restrict__ lo) {
    int idx = blockIdx.x*blockDim.x + threadIdx.x;
    if (idx >= RR*DM) return;
    int c = idx % DM;
    float v = (x[idx] - mean[c]) * rsqrtf(var[c] + EPS) * g[c] + b[c];
    v = v / (1.f + expf(-v));
    __nv_bfloat16 h, l; split2(v, h, l);
    hi[idx] = h; lo[idx] = l;
}

// ---------------- launch ----------------
extern "C" void kernel_launch(void* const* d_in, const int* in_sizes, int n_in,
                              void* d_out, int out_size) {
    const float* x_in      = (const float*)d_in[0];
    const float* cached    = (const float*)d_in[4];
    const float* ff1_nw    = (const float*)d_in[5];
    const float* ff1_w1    = (const float*)d_in[6];
    const float* ff1_b1    = (const float*)d_in[7];
    const float* ff1_w2    = (const float*)d_in[8];
    const float* ff1_b2    = (const float*)d_in[9];
    const float* attn_nw   = (const float*)d_in[10];
    const float* qkv_w     = (const float*)d_in[11];
    const float* out_w     = (const float*)d_in[12];
    const float* q_nw      = (const float*)d_in[13];
    const float* k_nw      = (const float*)d_in[14];
    const float* conv_nw   = (const float*)d_in[15];
    const float* pw1_w     = (const float*)d_in[16];
    const float* pw1_b     = (const float*)d_in[17];
    const float* dw_w      = (const float*)d_in[18];
    const float* dw_b      = (const float*)d_in[19];
    const float* bn_g      = (const float*)d_in[20];
    const float* bn_b      = (const float*)d_in[21];
    const float* pw2_w     = (const float*)d_in[22];
    const float* pw2_b     = (const float*)d_in[23];
    const float* ff2_nw    = (const float*)d_in[24];
    const float* ff2_w1    = (const float*)d_in[25];
    const float* ff2_b1    = (const float*)d_in[26];
    const float* ff2_w2    = (const float*)d_in[27];
    const float* ff2_b2    = (const float*)d_in[28];
    const float* out_nw    = (const float*)d_in[29];

    float* outx  = (float*)d_out;
    float* kvout = outx + (size_t)RR*DM;

    float *x_, *ff_, *qkv_, *glu_, *dw_, *mean_, *var_, *rs_, *rc_, *bnp1_, *bnp2_;
    __nv_bfloat16 *wth_, *wtl_, *abh_, *abl_, *a1h_, *a1l_, *qsh_, *qsl_, *ksh_, *ksl_, *vsh_, *vsl_;
    cudaGetSymbolAddress((void**)&x_,    g_x);
    cudaGetSymbolAddress((void**)&ff_,   g_ff);
    cudaGetSymbolAddress((void**)&qkv_,  g_qkv);
    cudaGetSymbolAddress((void**)&glu_,  g_glu);
    cudaGetSymbolAddress((void**)&dw_,   g_dw);
    cudaGetSymbolAddress((void**)&mean_, g_mean);
    cudaGetSymbolAddress((void**)&var_,  g_var);
    cudaGetSymbolAddress((void**)&rs_,   g_rs);
    cudaGetSymbolAddress((void**)&rc_,   g_rc);
    cudaGetSymbolAddress((void**)&bnp1_, g_bnp1);
    cudaGetSymbolAddress((void**)&bnp2_, g_bnp2);
    cudaGetSymbolAddress((void**)&wth_,  g_wth);
    cudaGetSymbolAddress((void**)&wtl_,  g_wtl);
    cudaGetSymbolAddress((void**)&abh_,  g_abh);
    cudaGetSymbolAddress((void**)&abl_,  g_abl);
    cudaGetSymbolAddress((void**)&a1h_,  g_a1h);
    cudaGetSymbolAddress((void**)&a1l_,  g_a1l);
    cudaGetSymbolAddress((void**)&qsh_,  g_qsh);
    cudaGetSymbolAddress((void**)&qsl_,  g_qsl);
    cudaGetSymbolAddress((void**)&ksh_,  g_ksh);
    cudaGetSymbolAddress((void**)&ksl_,  g_ksl);
    cudaGetSymbolAddress((void**)&vsh_,  g_vsh);
    cudaGetSymbolAddress((void**)&vsl_,  g_vsl);

    static int attr_set = 0;
    if (!attr_set) {
        cudaFuncSetAttribute(fa_mma_k, cudaFuncAttributeMaxDynamicSharedMemorySize, FA_SMEM);
        cudaFuncSetAttribute(tgemm_k<0,0>, cudaFuncAttributeMaxDynamicSharedMemorySize, GSM);
        cudaFuncSetAttribute(tgemm_k<1,1>, cudaFuncAttributeMaxDynamicSharedMemorySize, GSM);
        cudaFuncSetAttribute(tgemm_k<2,0>, cudaFuncAttributeMaxDynamicSharedMemorySize, GSM);
        attr_set = 1;
    }

    // weight offsets (transposed [N,K] layouts) — must match wsplit_all_k's segDst
    size_t o = 0;
    size_t off_qkv = o; o += (size_t)(3*NH*HD)*DM;
    size_t off_out = o; o += (size_t)DM*DM;
    size_t off_f1a = o; o += (size_t)FF*DM;
    size_t off_f1b = o; o += (size_t)DM*FF;
    size_t off_pw1 = o; o += (size_t)(2*DM)*DM;
    size_t off_pw2 = o; o += (size_t)DM*DM;
    size_t off_f2a = o; o += (size_t)FF*DM;
    size_t off_f2b = o; o += (size_t)DM*FF;

    wsplit_all_k<<<13248, 256>>>(qkv_w, out_w, ff1_w1, ff1_w2, pw1_w, pw2_w, ff2_w1, ff2_w2,
                                 wth_, wtl_);
    rope_table_k<<<(KVL*32 + 255)/256, 256>>>(rs_, rc_);

    cudaMemcpyAsync(x_, x_in, sizeof(float)*(size_t)RR*DM, cudaMemcpyDeviceToDevice, 0);

    const int EW = (RR*DM + 255)/256;

    // ---- FF1
    rmsnorm_split_k<<<RR, 256>>>(x_, ff1_nw, a1h_, a1l_);
    tgemm_k<1,1><<<dim3(FF/128, RR/128), 256, GSM>>>(a1h_, a1l_, wth_+off_f1a, wtl_+off_f1a,
                                                     ff1_b1, nullptr, nullptr, abh_, abl_, FF, DM);
    tgemm_k<2,0><<<dim3(DM/128, RR/128), 256, GSM>>>(abh_, abl_, wth_+off_f1b, wtl_+off_f1b,
                                                     ff1_b2, x_, x_, nullptr, nullptr, DM, FF);

    // ---- Attention
    rmsnorm_split_k<<<RR, 256>>>(x_, attn_nw, a1h_, a1l_);
    tgemm_k<0,0><<<dim3((3*NH*HD)/128, RR/128), 256, GSM>>>(a1h_, a1l_, wth_+off_qkv, wtl_+off_qkv,
                                                            nullptr, nullptr, qkv_, nullptr, nullptr,
                                                            3*NH*HD, DM);
    copy_cache_k<<<(BB*CCH*2*NH*HD + 255)/256, 256>>>(cached, kvout);
    qkv_post_k<<<RR*NH/4, 128>>>(qkv_, q_nw, k_nw, kvout, qsh_, qsl_, rs_, rc_);
    kvsplit_k<<<BB*KVL*NH/4, 128>>>(kvout, ksh_, ksl_, vsh_, vsl_, rs_, rc_);
    fa_mma_k<<<dim3(NN/64, NH, BB), 128, FA_SMEM>>>(qsh_, qsl_, ksh_, ksl_, vsh_, vsl_, a1h_, a1l_);
    tgemm_k<0,0><<<dim3(DM/128, RR/128), 256, GSM>>>(a1h_, a1l_, wth_+off_out, wtl_+off_out,
                                                     nullptr, x_, x_, nullptr, nullptr, DM, DM);

    // ---- Conv module
    rmsnorm_split_k<<<RR, 256>>>(x_, conv_nw, a1h_, a1l_);
    tgemm_k<0,0><<<dim3((2*DM)/128, RR/128), 256, GSM>>>(a1h_, a1l_, wth_+off_pw1, wtl_+off_pw1,
                                                         pw1_b, nullptr, ff_, nullptr, nullptr,
                                                         2*DM, DM);
    glu_k<<<EW, 256>>>(ff_, glu_);
    dwconv8_k<<<dim3(NN/8, BB), 256>>>(glu_, dw_w, dw_b, dw_);
    bnstats1_k<<<BN_BLKS, 256>>>(dw_, bnp1_, bnp2_);
    bnstats2_k<<<(DM + 255)/256, 256>>>(bnp1_, bnp2_, mean_, var_);
    bnapply_split_k<<<EW, 256>>>(dw_, mean_, var_, bn_g, bn_b, a1h_, a1l_);
    tgemm_k<0,0><<<dim3(DM/128, RR/128), 256, GSM>>>(a1h_, a1l_, wth_+off_pw2, wtl_+off_pw2,
                                                     pw2_b, nullptr, x_, nullptr, nullptr, DM, DM);

    // ---- FF2
    rmsnorm_split_k<<<RR, 256>>>(x_, ff2_nw, a1h_, a1l_);
    tgemm_k<1,1><<<dim3(FF/128, RR/128), 256, GSM>>>(a1h_, a1l_, wth_+off_f2a, wtl_+off_f2a,
                                                     ff2_b1, nullptr, nullptr, abh_, abl_, FF, DM);
    tgemm_k<2,0><<<dim3(DM/128, RR/128), 256, GSM>>>(abh_, abl_, wth_+off_f2b, wtl_+off_f2b,
                                                     ff2_b2, x_, x_, nullptr, nullptr, DM, FF);

    // ---- final rmsnorm -> output x
    rmsnorm_k<<<RR, 256>>>(x_, out_nw, outx);
}